// round 10
// baseline (speedup 1.0000x reference)
#include <cuda_runtime.h>
#include <cuda_fp16.h>
#include <math.h>
#include <stdint.h>

// Problem constants (fixed by setup_inputs)
#define N_NODES 32768
#define E_EDGES 524288
#define F_IN    128
#define D1      256
#define D2      128
#define NT      3
#define SEQ     16
#define NNG     512

// ---------------- scratch (device globals; no allocation allowed) ----------------
__device__ __half g_xh  [N_NODES * F_IN];            // 8 MB normalized x, fp16
__device__ __half g_agg [NT * N_NODES * F_IN];       // 24 MB aggregated xn, fp16
__device__ __half g_h1r [NT * N_NODES * D1];         // 48 MB relu(agg@W1+b1), fp16
__device__ __half g_h2  [NT * N_NODES * D2];         // 24 MB h1r@W2, fp16
__device__ float  g_deg [NT * N_NODES];
__device__ float  g_dis [NT * N_NODES];
__device__ int    g_counts[N_NODES];
__device__ int    g_rowptr[N_NODES + 1];
__device__ int    g_cursor[N_NODES];
__device__ float4 g_meta[E_EDGES];                   // {w0,w1,w2,src-as-float} CSR by dst
__device__ float  g_colsum[F_IN];
__device__ float  g_colsq [F_IN];
__device__ float  g_mean[F_IN];
__device__ float  g_rstd[F_IN];

// ---------------- helpers ----------------
__device__ __forceinline__ uint32_t f2tf32(float f) {
    uint32_t r;
    asm("cvt.rna.tf32.f32 %0, %1;" : "=r"(r) : "f"(f));
    return r;
}
__device__ __forceinline__ void mma_tf32(float* c,
    uint32_t a0, uint32_t a1, uint32_t a2, uint32_t a3,
    uint32_t b0, uint32_t b1)
{
    asm volatile(
        "mma.sync.aligned.m16n8k8.row.col.f32.tf32.tf32.f32 "
        "{%0,%1,%2,%3}, {%4,%5,%6,%7}, {%8,%9}, {%0,%1,%2,%3};"
        : "+f"(c[0]), "+f"(c[1]), "+f"(c[2]), "+f"(c[3])
        : "r"(a0), "r"(a1), "r"(a2), "r"(a3), "r"(b0), "r"(b1));
}
__device__ __forceinline__ uint32_t pack_h2(float a, float b) {
    __half2 h = __floats2half2_rn(a, b);
    return *(uint32_t*)&h;
}
__device__ __forceinline__ float2 uph2(uint32_t u) {
    return __half22float2(*(__half2*)&u);
}

// ---------------- small prep kernels ----------------
__global__ void zero_kernel() {
    int i = blockIdx.x * 256 + threadIdx.x;
    if (i < N_NODES)      g_counts[i] = 0;
    if (i < NT * N_NODES) g_deg[i] = 0.0f;
    if (i < F_IN) { g_colsum[i] = 0.0f; g_colsq[i] = 0.0f; }
}

__global__ void stats_kernel(const float* __restrict__ x) {
    int c  = threadIdx.x;
    int r0 = blockIdx.x * 256;
    float s = 0.0f, q = 0.0f;
    for (int r = 0; r < 256; r++) {
        float v = x[(r0 + r) * F_IN + c];
        s += v; q += v * v;
    }
    atomicAdd(&g_colsum[c], s);
    atomicAdd(&g_colsq[c],  q);
}

__global__ void finstats_kernel() {
    int c = threadIdx.x;
    float n = (float)N_NODES;
    float mean = g_colsum[c] / n;
    float var  = (g_colsq[c] - n * mean * mean) / (n - 1.0f);  // ddof=1
    g_mean[c] = mean;
    g_rstd[c] = rsqrtf(var);
}

// normalize x -> fp16 table
__global__ void xnorm_kernel(const float* __restrict__ x) {
    int i  = blockIdx.x * 256 + threadIdx.x;  // float4 index
    int c4 = (i & 31) * 4;
    float4 v = ((const float4*)x)[i];
    v.x = (v.x - g_mean[c4 + 0]) * g_rstd[c4 + 0];
    v.y = (v.y - g_mean[c4 + 1]) * g_rstd[c4 + 1];
    v.z = (v.z - g_mean[c4 + 2]) * g_rstd[c4 + 2];
    v.w = (v.w - g_mean[c4 + 3]) * g_rstd[c4 + 3];
    uint2 o = make_uint2(pack_h2(v.x, v.y), pack_h2(v.z, v.w));
    ((uint2*)g_xh)[i] = o;
}

__global__ void hist_kernel(const int* __restrict__ ei, const float* __restrict__ ea) {
    int e = blockIdx.x * 256 + threadIdx.x;
    if (e >= E_EDGES) return;
    int dst = ei[E_EDGES + e];
    atomicAdd(&g_counts[dst], 1);
    atomicAdd(&g_deg[0 * N_NODES + dst], fabsf(ea[3 * e + 0]));
    atomicAdd(&g_deg[1 * N_NODES + dst], fabsf(ea[3 * e + 1]));
    atomicAdd(&g_deg[2 * N_NODES + dst], fabsf(ea[3 * e + 2]));
}

__global__ void scan_kernel() {
    __shared__ int sums[1024];
    int tid  = threadIdx.x;
    int base = tid * 32;
    int vals[32];
    int s = 0;
#pragma unroll
    for (int i = 0; i < 32; i++) { int v = g_counts[base + i]; vals[i] = s; s += v; }
    sums[tid] = s;
    __syncthreads();
    for (int off = 1; off < 1024; off <<= 1) {
        int v = (tid >= off) ? sums[tid - off] : 0;
        __syncthreads();
        sums[tid] += v;
        __syncthreads();
    }
    int ex = (tid > 0) ? sums[tid - 1] : 0;
#pragma unroll
    for (int i = 0; i < 32; i++) {
        int p = ex + vals[i];
        g_rowptr[base + i] = p;
        g_cursor[base + i] = p;
    }
    if (tid == 1023) g_rowptr[N_NODES] = sums[1023];
}

__global__ void dis_kernel() {
    int i = blockIdx.x * 256 + threadIdx.x;
    if (i < NT * N_NODES) g_dis[i] = rsqrtf(g_deg[i] + 1.0f);
}

__global__ void fill_kernel(const int* __restrict__ ei, const float* __restrict__ ea) {
    int e = blockIdx.x * 256 + threadIdx.x;
    if (e >= E_EDGES) return;
    int src = ei[e];
    int dst = ei[E_EDGES + e];
    int pos = atomicAdd(&g_cursor[dst], 1);
    float4 m;
    m.x = g_dis[0 * N_NODES + src] * fabsf(ea[3 * e + 0]) * g_dis[0 * N_NODES + dst];
    m.y = g_dis[1 * N_NODES + src] * fabsf(ea[3 * e + 1]) * g_dis[1 * N_NODES + dst];
    m.z = g_dis[2 * N_NODES + src] * fabsf(ea[3 * e + 2]) * g_dis[2 * N_NODES + dst];
    m.w = __int_as_float(src);
    g_meta[pos] = m;
}

// ---------------- fused 3-type aggregation of fp16 xn (1 warp/node, R8 config) ----------------
__global__ void gather0_kernel() {
    int lane = threadIdx.x & 31;
    int v    = blockIdx.x * 8 + (threadIdx.x >> 5);

    const uint2* __restrict__ xh = (const uint2*)g_xh;   // 32 uint2 per row (128 halves)
    int beg = g_rowptr[v];
    int end = g_rowptr[v + 1];

    float4 a0 = make_float4(0.f, 0.f, 0.f, 0.f);
    float4 a1 = make_float4(0.f, 0.f, 0.f, 0.f);
    float4 a2 = make_float4(0.f, 0.f, 0.f, 0.f);

    int j = beg;
    for (; j + 1 < end; j += 2) {
        float4 mA = __ldg(&g_meta[j]);
        float4 mB = __ldg(&g_meta[j + 1]);
        uint2 rA = xh[__float_as_int(mA.w) * 32 + lane];
        uint2 rB = xh[__float_as_int(mB.w) * 32 + lane];
        float2 fA0 = uph2(rA.x), fA1 = uph2(rA.y);
        float2 fB0 = uph2(rB.x), fB1 = uph2(rB.y);
        a0.x = fmaf(mA.x, fA0.x, a0.x); a0.y = fmaf(mA.x, fA0.y, a0.y);
        a0.z = fmaf(mA.x, fA1.x, a0.z); a0.w = fmaf(mA.x, fA1.y, a0.w);
        a1.x = fmaf(mA.y, fA0.x, a1.x); a1.y = fmaf(mA.y, fA0.y, a1.y);
        a1.z = fmaf(mA.y, fA1.x, a1.z); a1.w = fmaf(mA.y, fA1.y, a1.w);
        a2.x = fmaf(mA.z, fA0.x, a2.x); a2.y = fmaf(mA.z, fA0.y, a2.y);
        a2.z = fmaf(mA.z, fA1.x, a2.z); a2.w = fmaf(mA.z, fA1.y, a2.w);
        a0.x = fmaf(mB.x, fB0.x, a0.x); a0.y = fmaf(mB.x, fB0.y, a0.y);
        a0.z = fmaf(mB.x, fB1.x, a0.z); a0.w = fmaf(mB.x, fB1.y, a0.w);
        a1.x = fmaf(mB.y, fB0.x, a1.x); a1.y = fmaf(mB.y, fB0.y, a1.y);
        a1.z = fmaf(mB.y, fB1.x, a1.z); a1.w = fmaf(mB.y, fB1.y, a1.w);
        a2.x = fmaf(mB.z, fB0.x, a2.x); a2.y = fmaf(mB.z, fB0.y, a2.y);
        a2.z = fmaf(mB.z, fB1.x, a2.z); a2.w = fmaf(mB.z, fB1.y, a2.w);
    }
    if (j < end) {
        float4 m = __ldg(&g_meta[j]);
        uint2 r = xh[__float_as_int(m.w) * 32 + lane];
        float2 f0 = uph2(r.x), f1 = uph2(r.y);
        a0.x = fmaf(m.x, f0.x, a0.x); a0.y = fmaf(m.x, f0.y, a0.y);
        a0.z = fmaf(m.x, f1.x, a0.z); a0.w = fmaf(m.x, f1.y, a0.w);
        a1.x = fmaf(m.y, f0.x, a1.x); a1.y = fmaf(m.y, f0.y, a1.y);
        a1.z = fmaf(m.y, f1.x, a1.z); a1.w = fmaf(m.y, f1.y, a1.w);
        a2.x = fmaf(m.z, f0.x, a2.x); a2.y = fmaf(m.z, f0.y, a2.y);
        a2.z = fmaf(m.z, f1.x, a2.z); a2.w = fmaf(m.z, f1.y, a2.w);
    }

    uint2 rv = xh[v * 32 + lane];
    float2 v0 = uph2(rv.x), v1 = uph2(rv.y);
    float i0 = g_dis[0 * N_NODES + v]; i0 *= i0;
    float i1 = g_dis[1 * N_NODES + v]; i1 *= i1;
    float i2 = g_dis[2 * N_NODES + v]; i2 *= i2;
    a0.x = fmaf(i0, v0.x, a0.x); a0.y = fmaf(i0, v0.y, a0.y);
    a0.z = fmaf(i0, v1.x, a0.z); a0.w = fmaf(i0, v1.y, a0.w);
    a1.x = fmaf(i1, v0.x, a1.x); a1.y = fmaf(i1, v0.y, a1.y);
    a1.z = fmaf(i1, v1.x, a1.z); a1.w = fmaf(i1, v1.y, a1.w);
    a2.x = fmaf(i2, v0.x, a2.x); a2.y = fmaf(i2, v0.y, a2.y);
    a2.z = fmaf(i2, v1.x, a2.z); a2.w = fmaf(i2, v1.y, a2.w);

    uint2* o = (uint2*)g_agg;
    o[(0 * N_NODES + v) * 32 + lane] = make_uint2(pack_h2(a0.x, a0.y), pack_h2(a0.z, a0.w));
    o[(1 * N_NODES + v) * 32 + lane] = make_uint2(pack_h2(a1.x, a1.y), pack_h2(a1.z, a1.w));
    o[(2 * N_NODES + v) * 32 + lane] = make_uint2(pack_h2(a2.x, a2.y), pack_h2(a2.z, a2.w));
}

// ---------------- tf32 mma.sync GEMM with register-prefetch double buffering ----------------
// C[M,N](fp16) = A(fp16)[M,K] @ W(fp32)[K,N]. Block 128x128, 8 warps, warp tile 64x32, K chunk 32.
__global__ void __launch_bounds__(256) gemm_mma(
    const __half* __restrict__ Abase, long long Astride,
    const float* __restrict__ Wbase, long long Wstride,
    __half* __restrict__ Cbase, long long Cstride,
    const float* __restrict__ biasBase, int biasStride,
    int M, int N, int K, int doRelu)
{
    __shared__ uint32_t As[128][36];   // [m][k] tf32
    __shared__ uint32_t Bs[32][136];   // [k][n] tf32

    const int t = blockIdx.z;
    const __half* A = Abase + (long long)t * Astride;
    const float*  W = Wbase + (long long)t * Wstride;
    __half*       C = Cbase + (long long)t * Cstride;

    const int tid  = threadIdx.x;
    const int wid  = tid >> 5;
    const int lane = tid & 31;
    const int gid  = lane >> 2;
    const int tig  = lane & 3;
    const int wm0  = (wid & 1) * 64;
    const int wn0  = (wid >> 1) * 32;
    const int bm0  = blockIdx.y * 128;
    const int bn0  = blockIdx.x * 128;

    // per-thread load coords
    const int ar = tid >> 2;            // A rows: ar, ar+64 (wait: 512 loads over 2 iters)
    const int ac8 = tid & 3;            // 8-half column group
    const int bk = tid >> 5;            // B rows bk, bk+8, bk+16, bk+24
    const int bn4 = tid & 31;           // 4-float column group

    float acc[4][4][4];
#pragma unroll
    for (int i = 0; i < 4; i++)
#pragma unroll
        for (int j = 0; j < 4; j++)
#pragma unroll
            for (int q = 0; q < 4; q++) acc[i][j][q] = 0.0f;

    uint4  aR[2];
    float4 bR[4];

    // prologue: load chunk 0
    {
        const __half* ap = A + (long long)(bm0 + ar) * K + ac8 * 8;
        aR[0] = *(const uint4*)(ap);
        aR[1] = *(const uint4*)(ap + 64LL * K);
#pragma unroll
        for (int q = 0; q < 4; q++)
            bR[q] = *(const float4*)(W + (long long)(bk + q * 8) * N + bn0 + bn4 * 4);
    }
    // store chunk 0
    {
#pragma unroll
        for (int h = 0; h < 2; h++) {
            int r = ar + h * 64;
            const uint32_t* pw = &aR[h].x;
#pragma unroll
            for (int q = 0; q < 4; q++) {
                float2 f = __half22float2(*(const __half2*)&pw[q]);
                As[r][ac8 * 8 + q * 2]     = f2tf32(f.x);
                As[r][ac8 * 8 + q * 2 + 1] = f2tf32(f.y);
            }
        }
#pragma unroll
        for (int q = 0; q < 4; q++) {
            uint4 o = make_uint4(f2tf32(bR[q].x), f2tf32(bR[q].y), f2tf32(bR[q].z), f2tf32(bR[q].w));
            *(uint4*)&Bs[bk + q * 8][bn4 * 4] = o;
        }
    }
    __syncthreads();

    const int nch = K >> 5;
    for (int c = 0; c < nch; c++) {
        bool more = (c + 1 < nch);
        if (more) {
            int k0 = (c + 1) << 5;
            const __half* ap = A + (long long)(bm0 + ar) * K + k0 + ac8 * 8;
            aR[0] = *(const uint4*)(ap);
            aR[1] = *(const uint4*)(ap + 64LL * K);
#pragma unroll
            for (int q = 0; q < 4; q++)
                bR[q] = *(const float4*)(W + (long long)(k0 + bk + q * 8) * N + bn0 + bn4 * 4);
        }

#pragma unroll
        for (int ks = 0; ks < 4; ks++) {
            int kk = ks * 8;
            uint32_t bf[4][2];
#pragma unroll
            for (int nf = 0; nf < 4; nf++) {
                bf[nf][0] = Bs[kk + tig][wn0 + nf * 8 + gid];
                bf[nf][1] = Bs[kk + tig + 4][wn0 + nf * 8 + gid];
            }
#pragma unroll
            for (int mf = 0; mf < 4; mf++) {
                int r = wm0 + mf * 16 + gid;
                uint32_t a0 = As[r][kk + tig];
                uint32_t a1 = As[r + 8][kk + tig];
                uint32_t a2 = As[r][kk + tig + 4];
                uint32_t a3 = As[r + 8][kk + tig + 4];
#pragma unroll
                for (int nf = 0; nf < 4; nf++)
                    mma_tf32(acc[mf][nf], a0, a1, a2, a3, bf[nf][0], bf[nf][1]);
            }
        }

        if (more) {
            __syncthreads();
#pragma unroll
            for (int h = 0; h < 2; h++) {
                int r = ar + h * 64;
                const uint32_t* pw = &aR[h].x;
#pragma unroll
                for (int q = 0; q < 4; q++) {
                    float2 f = __half22float2(*(const __half2*)&pw[q]);
                    As[r][ac8 * 8 + q * 2]     = f2tf32(f.x);
                    As[r][ac8 * 8 + q * 2 + 1] = f2tf32(f.y);
                }
            }
#pragma unroll
            for (int q = 0; q < 4; q++) {
                uint4 o = make_uint4(f2tf32(bR[q].x), f2tf32(bR[q].y), f2tf32(bR[q].z), f2tf32(bR[q].w));
                *(uint4*)&Bs[bk + q * 8][bn4 * 4] = o;
            }
            __syncthreads();
        }
    }

    // epilogue: bias + relu, __half2 stores
#pragma unroll
    for (int mf = 0; mf < 4; mf++) {
        int row = bm0 + wm0 + mf * 16 + gid;
#pragma unroll
        for (int nf = 0; nf < 4; nf++) {
            int col = bn0 + wn0 + nf * 8 + tig * 2;
            float b0 = 0.0f, b1 = 0.0f;
            if (biasBase) {
                const float* bp = biasBase + (long long)t * biasStride + col;
                b0 = bp[0]; b1 = bp[1];
            }
            float o0 = acc[mf][nf][0] + b0;
            float o1 = acc[mf][nf][1] + b1;
            float o2 = acc[mf][nf][2] + b0;
            float o3 = acc[mf][nf][3] + b1;
            if (doRelu) {
                o0 = fmaxf(o0, 0.f); o1 = fmaxf(o1, 0.f);
                o2 = fmaxf(o2, 0.f); o3 = fmaxf(o3, 0.f);
            }
            *(__half2*)(C + (long long)row * N + col)       = __floats2half2_rn(o0, o1);
            *(__half2*)(C + (long long)(row + 8) * N + col) = __floats2half2_rn(o2, o3);
        }
    }
}

// ---------------- layer-2 gather: all 3 types fused (R8 config), + output permutation ---------
__global__ void gather2_kernel(const float* __restrict__ b2, float* __restrict__ out) {
    int lane = threadIdx.x & 31;
    int v    = blockIdx.x * 8 + (threadIdx.x >> 5);

    const uint2* __restrict__ h2a = (const uint2*)(g_h2);
    const uint2* __restrict__ h2b = (const uint2*)(g_h2 + (long long)N_NODES * D2);
    const uint2* __restrict__ h2c = (const uint2*)(g_h2 + 2LL * N_NODES * D2);
    int beg = g_rowptr[v];
    int end = g_rowptr[v + 1];

    float4 a0 = make_float4(0.f, 0.f, 0.f, 0.f);
    float4 a1 = make_float4(0.f, 0.f, 0.f, 0.f);
    float4 a2 = make_float4(0.f, 0.f, 0.f, 0.f);

    for (int j = beg; j < end; j++) {
        float4 m = __ldg(&g_meta[j]);
        int src = __float_as_int(m.w);
        uint2 r0 = h2a[src * 32 + lane];
        uint2 r1 = h2b[src * 32 + lane];
        uint2 r2 = h2c[src * 32 + lane];
        float2 f00 = uph2(r0.x), f01 = uph2(r0.y);
        float2 f10 = uph2(r1.x), f11 = uph2(r1.y);
        float2 f20 = uph2(r2.x), f21 = uph2(r2.y);
        a0.x = fmaf(m.x, f00.x, a0.x); a0.y = fmaf(m.x, f00.y, a0.y);
        a0.z = fmaf(m.x, f01.x, a0.z); a0.w = fmaf(m.x, f01.y, a0.w);
        a1.x = fmaf(m.y, f10.x, a1.x); a1.y = fmaf(m.y, f10.y, a1.y);
        a1.z = fmaf(m.y, f11.x, a1.z); a1.w = fmaf(m.y, f11.y, a1.w);
        a2.x = fmaf(m.z, f20.x, a2.x); a2.y = fmaf(m.z, f20.y, a2.y);
        a2.z = fmaf(m.z, f21.x, a2.z); a2.w = fmaf(m.z, f21.y, a2.w);
    }

    float i0 = g_dis[0 * N_NODES + v]; i0 *= i0;
    float i1 = g_dis[1 * N_NODES + v]; i1 *= i1;
    float i2 = g_dis[2 * N_NODES + v]; i2 *= i2;
    uint2 sr0 = h2a[v * 32 + lane];
    uint2 sr1 = h2b[v * 32 + lane];
    uint2 sr2 = h2c[v * 32 + lane];
    float2 s00 = uph2(sr0.x), s01 = uph2(sr0.y);
    float2 s10 = uph2(sr1.x), s11 = uph2(sr1.y);
    float2 s20 = uph2(sr2.x), s21 = uph2(sr2.y);
    float4 bb0 = ((const float4*)(b2 + 0 * D2))[lane];
    float4 bb1 = ((const float4*)(b2 + 1 * D2))[lane];
    float4 bb2 = ((const float4*)(b2 + 2 * D2))[lane];

    a0.x = fmaxf(fmaf(i0, s00.x, a0.x) + bb0.x, 0.f);
    a0.y = fmaxf(fmaf(i0, s00.y, a0.y) + bb0.y, 0.f);
    a0.z = fmaxf(fmaf(i0, s01.x, a0.z) + bb0.z, 0.f);
    a0.w = fmaxf(fmaf(i0, s01.y, a0.w) + bb0.w, 0.f);
    a1.x = fmaxf(fmaf(i1, s10.x, a1.x) + bb1.x, 0.f);
    a1.y = fmaxf(fmaf(i1, s10.y, a1.y) + bb1.y, 0.f);
    a1.z = fmaxf(fmaf(i1, s11.x, a1.z) + bb1.z, 0.f);
    a1.w = fmaxf(fmaf(i1, s11.y, a1.w) + bb1.w, 0.f);
    a2.x = fmaxf(fmaf(i2, s20.x, a2.x) + bb2.x, 0.f);
    a2.y = fmaxf(fmaf(i2, s20.y, a2.y) + bb2.y, 0.f);
    a2.z = fmaxf(fmaf(i2, s21.x, a2.z) + bb2.z, 0.f);
    a2.w = fmaxf(fmaf(i2, s21.y, a2.w) + bb2.w, 0.f);

    int bt = v >> 13;
    int sq = (v >> 9) & 15;
    int vv = v & 511;
    int orow = bt * NNG + vv;
    long long base = ((long long)(orow * SEQ + sq)) * (NT * D2) + lane * 4;
    *(float4*)(out + base)          = a0;
    *(float4*)(out + base + D2)     = a1;
    *(float4*)(out + base + 2 * D2) = a2;
}

// ---------------- launch ----------------
extern "C" void kernel_launch(void* const* d_in, const int* in_sizes, int n_in,
                              void* d_out, int out_size) {
    const float* x  = (const float*)d_in[0];
    const float* ea = (const float*)d_in[1];
    const float* W1 = (const float*)d_in[2];
    const float* b1 = (const float*)d_in[3];
    const float* W2 = (const float*)d_in[4];
    const float* b2 = (const float*)d_in[5];
    const int*   ei = (const int*)d_in[6];
    float* out = (float*)d_out;

    __half *agg, *h1r, *h2;
    cudaGetSymbolAddress((void**)&agg, g_agg);
    cudaGetSymbolAddress((void**)&h1r, g_h1r);
    cudaGetSymbolAddress((void**)&h2,  g_h2);

    zero_kernel     <<<384, 256>>>();
    stats_kernel    <<<128, 128>>>(x);
    finstats_kernel <<<1, 128>>>();
    xnorm_kernel    <<<4096, 256>>>(x);
    hist_kernel     <<<E_EDGES / 256, 256>>>(ei, ea);
    scan_kernel     <<<1, 1024>>>();
    dis_kernel      <<<384, 256>>>();
    fill_kernel     <<<E_EDGES / 256, 256>>>(ei, ea);
    gather0_kernel  <<<N_NODES / 8, 256>>>();

    // h1r_t = relu(agg_t @ W1_t + b1_t)   [32768,128]@[128,256] -> fp16
    gemm_mma<<<dim3(D1 / 128, N_NODES / 128, NT), 256>>>(
        agg, (long long)N_NODES * F_IN, W1, (long long)F_IN * D1,
        h1r, (long long)N_NODES * D1, b1, D1,
        N_NODES, D1, F_IN, 1);

    // h2_t = h1r_t @ W2_t   [32768,256]@[256,128] -> fp16
    gemm_mma<<<dim3(D2 / 128, N_NODES / 128, NT), 256>>>(
        h1r, (long long)N_NODES * D1, W2, (long long)D1 * D2,
        h2, (long long)N_NODES * D2, (const float*)nullptr, 0,
        N_NODES, D2, D1, 0);

    gather2_kernel<<<N_NODES / 8, 256>>>(b2, out);
}

// round 11
// speedup vs baseline: 1.0983x; 1.0983x over previous
#include <cuda_runtime.h>
#include <cuda_fp16.h>
#include <math.h>
#include <stdint.h>

// Problem constants (fixed by setup_inputs)
#define N_NODES 32768
#define E_EDGES 524288
#define F_IN    128
#define D1      256
#define D2      128
#define NT      3
#define SEQ     16
#define NNG     512

// ---------------- scratch (device globals; no allocation allowed) ----------------
__device__ __half g_xh  [N_NODES * F_IN];            // 8 MB normalized x, fp16
__device__ __half g_agg [NT * N_NODES * F_IN];       // 24 MB aggregated xn, fp16
__device__ __half g_h1r [NT * N_NODES * D1];         // 48 MB relu(agg@W1+b1), fp16
__device__ __half g_h2  [NT * N_NODES * D2];         // 24 MB h1r@W2, fp16
__device__ float  g_deg [NT * N_NODES];
__device__ float  g_dis [NT * N_NODES];
__device__ int    g_counts[N_NODES];
__device__ int    g_rowptr[N_NODES + 1];
__device__ int    g_cursor[N_NODES];
__device__ float4 g_meta[E_EDGES];                   // {w0,w1,w2,src-as-float} CSR by dst
__device__ float  g_colsum[F_IN];
__device__ float  g_colsq [F_IN];
__device__ float  g_mean[F_IN];
__device__ float  g_rstd[F_IN];

// ---------------- helpers ----------------
__device__ __forceinline__ uint32_t f2tf32(float f) {
    uint32_t r;
    asm("cvt.rna.tf32.f32 %0, %1;" : "=r"(r) : "f"(f));
    return r;
}
__device__ __forceinline__ void mma_tf32(float* c,
    uint32_t a0, uint32_t a1, uint32_t a2, uint32_t a3,
    uint32_t b0, uint32_t b1)
{
    asm volatile(
        "mma.sync.aligned.m16n8k8.row.col.f32.tf32.tf32.f32 "
        "{%0,%1,%2,%3}, {%4,%5,%6,%7}, {%8,%9}, {%0,%1,%2,%3};"
        : "+f"(c[0]), "+f"(c[1]), "+f"(c[2]), "+f"(c[3])
        : "r"(a0), "r"(a1), "r"(a2), "r"(a3), "r"(b0), "r"(b1));
}
__device__ __forceinline__ uint32_t pack_h2(float a, float b) {
    __half2 h = __floats2half2_rn(a, b);
    return *(uint32_t*)&h;
}
__device__ __forceinline__ float2 uph2(uint32_t u) {
    return __half22float2(*(__half2*)&u);
}

// ---------------- prep kernels (merged, role-split grids) ----------------
__global__ void zero_kernel() {
    int i = blockIdx.x * 256 + threadIdx.x;
    if (i < N_NODES)      g_counts[i] = 0;
    if (i < NT * N_NODES) g_deg[i] = 0.0f;
    if (i < F_IN) { g_colsum[i] = 0.0f; g_colsq[i] = 0.0f; }
}

// prep1: blocks [0,2048) = edge histogram + weighted degree; blocks [2048,2176) = x column stats
__global__ void prep1_kernel(const float* __restrict__ x,
                             const int* __restrict__ ei, const float* __restrict__ ea) {
    int bid = blockIdx.x;
    if (bid < E_EDGES / 256) {
        int e = bid * 256 + threadIdx.x;
        int dst = ei[E_EDGES + e];
        atomicAdd(&g_counts[dst], 1);
        atomicAdd(&g_deg[0 * N_NODES + dst], fabsf(ea[3 * e + 0]));
        atomicAdd(&g_deg[1 * N_NODES + dst], fabsf(ea[3 * e + 1]));
        atomicAdd(&g_deg[2 * N_NODES + dst], fabsf(ea[3 * e + 2]));
    } else {
        int sbid = bid - E_EDGES / 256;              // 0..127
        int c    = threadIdx.x & 127;
        int half = threadIdx.x >> 7;
        int r0   = sbid * 256 + half * 128;
        float s = 0.0f, q = 0.0f;
        for (int r = 0; r < 128; r++) {
            float v = x[(r0 + r) * F_IN + c];
            s += v; q += v * v;
        }
        atomicAdd(&g_colsum[c], s);
        atomicAdd(&g_colsq[c],  q);
    }
}

// prep2: block 0 = exclusive scan of counts; block 1 = finalize mean/rstd
__global__ void prep2_kernel() {
    if (blockIdx.x == 0) {
        __shared__ int sums[1024];
        int tid  = threadIdx.x;
        int base = tid * 32;
        int vals[32];
        int s = 0;
#pragma unroll
        for (int i = 0; i < 32; i++) { int v = g_counts[base + i]; vals[i] = s; s += v; }
        sums[tid] = s;
        __syncthreads();
        for (int off = 1; off < 1024; off <<= 1) {
            int v = (tid >= off) ? sums[tid - off] : 0;
            __syncthreads();
            sums[tid] += v;
            __syncthreads();
        }
        int ex = (tid > 0) ? sums[tid - 1] : 0;
#pragma unroll
        for (int i = 0; i < 32; i++) {
            int p = ex + vals[i];
            g_rowptr[base + i] = p;
            g_cursor[base + i] = p;
        }
        if (tid == 1023) g_rowptr[N_NODES] = sums[1023];
    } else {
        if (threadIdx.x < F_IN) {
            int c = threadIdx.x;
            float n = (float)N_NODES;
            float mean = g_colsum[c] / n;
            float var  = (g_colsq[c] - n * mean * mean) / (n - 1.0f);  // ddof=1
            g_mean[c] = mean;
            g_rstd[c] = rsqrtf(var);
        }
    }
}

// prep3: blocks [0,4096) = normalize x -> fp16; blocks [4096,4480) = dis = rsqrt(deg+1)
__global__ void prep3_kernel(const float* __restrict__ x) {
    int bid = blockIdx.x;
    if (bid < 4096) {
        int i  = bid * 256 + threadIdx.x;  // float4 index
        int c4 = (i & 31) * 4;
        float4 v = ((const float4*)x)[i];
        v.x = (v.x - g_mean[c4 + 0]) * g_rstd[c4 + 0];
        v.y = (v.y - g_mean[c4 + 1]) * g_rstd[c4 + 1];
        v.z = (v.z - g_mean[c4 + 2]) * g_rstd[c4 + 2];
        v.w = (v.w - g_mean[c4 + 3]) * g_rstd[c4 + 3];
        ((uint2*)g_xh)[i] = make_uint2(pack_h2(v.x, v.y), pack_h2(v.z, v.w));
    } else {
        int i = (bid - 4096) * 256 + threadIdx.x;
        if (i < NT * N_NODES) g_dis[i] = rsqrtf(g_deg[i] + 1.0f);
    }
}

__global__ void fill_kernel(const int* __restrict__ ei, const float* __restrict__ ea) {
    int e = blockIdx.x * 256 + threadIdx.x;
    if (e >= E_EDGES) return;
    int src = ei[e];
    int dst = ei[E_EDGES + e];
    int pos = atomicAdd(&g_cursor[dst], 1);
    float4 m;
    m.x = g_dis[0 * N_NODES + src] * fabsf(ea[3 * e + 0]) * g_dis[0 * N_NODES + dst];
    m.y = g_dis[1 * N_NODES + src] * fabsf(ea[3 * e + 1]) * g_dis[1 * N_NODES + dst];
    m.z = g_dis[2 * N_NODES + src] * fabsf(ea[3 * e + 2]) * g_dis[2 * N_NODES + dst];
    m.w = __int_as_float(src);
    g_meta[pos] = m;
}

// ---------------- fused 3-type aggregation of fp16 xn (1 warp/node, R8 config) ----------------
__global__ void gather0_kernel() {
    int lane = threadIdx.x & 31;
    int v    = blockIdx.x * 8 + (threadIdx.x >> 5);

    const uint2* __restrict__ xh = (const uint2*)g_xh;   // 32 uint2 per row (128 halves)
    int beg = g_rowptr[v];
    int end = g_rowptr[v + 1];

    float4 a0 = make_float4(0.f, 0.f, 0.f, 0.f);
    float4 a1 = make_float4(0.f, 0.f, 0.f, 0.f);
    float4 a2 = make_float4(0.f, 0.f, 0.f, 0.f);

    int j = beg;
    for (; j + 1 < end; j += 2) {
        float4 mA = __ldg(&g_meta[j]);
        float4 mB = __ldg(&g_meta[j + 1]);
        uint2 rA = xh[__float_as_int(mA.w) * 32 + lane];
        uint2 rB = xh[__float_as_int(mB.w) * 32 + lane];
        float2 fA0 = uph2(rA.x), fA1 = uph2(rA.y);
        float2 fB0 = uph2(rB.x), fB1 = uph2(rB.y);
        a0.x = fmaf(mA.x, fA0.x, a0.x); a0.y = fmaf(mA.x, fA0.y, a0.y);
        a0.z = fmaf(mA.x, fA1.x, a0.z); a0.w = fmaf(mA.x, fA1.y, a0.w);
        a1.x = fmaf(mA.y, fA0.x, a1.x); a1.y = fmaf(mA.y, fA0.y, a1.y);
        a1.z = fmaf(mA.y, fA1.x, a1.z); a1.w = fmaf(mA.y, fA1.y, a1.w);
        a2.x = fmaf(mA.z, fA0.x, a2.x); a2.y = fmaf(mA.z, fA0.y, a2.y);
        a2.z = fmaf(mA.z, fA1.x, a2.z); a2.w = fmaf(mA.z, fA1.y, a2.w);
        a0.x = fmaf(mB.x, fB0.x, a0.x); a0.y = fmaf(mB.x, fB0.y, a0.y);
        a0.z = fmaf(mB.x, fB1.x, a0.z); a0.w = fmaf(mB.x, fB1.y, a0.w);
        a1.x = fmaf(mB.y, fB0.x, a1.x); a1.y = fmaf(mB.y, fB0.y, a1.y);
        a1.z = fmaf(mB.y, fB1.x, a1.z); a1.w = fmaf(mB.y, fB1.y, a1.w);
        a2.x = fmaf(mB.z, fB0.x, a2.x); a2.y = fmaf(mB.z, fB0.y, a2.y);
        a2.z = fmaf(mB.z, fB1.x, a2.z); a2.w = fmaf(mB.z, fB1.y, a2.w);
    }
    if (j < end) {
        float4 m = __ldg(&g_meta[j]);
        uint2 r = xh[__float_as_int(m.w) * 32 + lane];
        float2 f0 = uph2(r.x), f1 = uph2(r.y);
        a0.x = fmaf(m.x, f0.x, a0.x); a0.y = fmaf(m.x, f0.y, a0.y);
        a0.z = fmaf(m.x, f1.x, a0.z); a0.w = fmaf(m.x, f1.y, a0.w);
        a1.x = fmaf(m.y, f0.x, a1.x); a1.y = fmaf(m.y, f0.y, a1.y);
        a1.z = fmaf(m.y, f1.x, a1.z); a1.w = fmaf(m.y, f1.y, a1.w);
        a2.x = fmaf(m.z, f0.x, a2.x); a2.y = fmaf(m.z, f0.y, a2.y);
        a2.z = fmaf(m.z, f1.x, a2.z); a2.w = fmaf(m.z, f1.y, a2.w);
    }

    uint2 rv = xh[v * 32 + lane];
    float2 v0 = uph2(rv.x), v1 = uph2(rv.y);
    float i0 = g_dis[0 * N_NODES + v]; i0 *= i0;
    float i1 = g_dis[1 * N_NODES + v]; i1 *= i1;
    float i2 = g_dis[2 * N_NODES + v]; i2 *= i2;
    a0.x = fmaf(i0, v0.x, a0.x); a0.y = fmaf(i0, v0.y, a0.y);
    a0.z = fmaf(i0, v1.x, a0.z); a0.w = fmaf(i0, v1.y, a0.w);
    a1.x = fmaf(i1, v0.x, a1.x); a1.y = fmaf(i1, v0.y, a1.y);
    a1.z = fmaf(i1, v1.x, a1.z); a1.w = fmaf(i1, v1.y, a1.w);
    a2.x = fmaf(i2, v0.x, a2.x); a2.y = fmaf(i2, v0.y, a2.y);
    a2.z = fmaf(i2, v1.x, a2.z); a2.w = fmaf(i2, v1.y, a2.w);

    uint2* o = (uint2*)g_agg;
    o[(0 * N_NODES + v) * 32 + lane] = make_uint2(pack_h2(a0.x, a0.y), pack_h2(a0.z, a0.w));
    o[(1 * N_NODES + v) * 32 + lane] = make_uint2(pack_h2(a1.x, a1.y), pack_h2(a1.z, a1.w));
    o[(2 * N_NODES + v) * 32 + lane] = make_uint2(pack_h2(a2.x, a2.y), pack_h2(a2.z, a2.w));
}

// ---------------- tf32 mma.sync GEMM (R8 version, unchanged) ----------------
// C[M,N](fp16) = A(fp16)[M,K] @ W(fp32)[K,N]. Block 128x128, 8 warps, warp tile 64x32, K chunk 32.
__global__ void __launch_bounds__(256) gemm_mma(
    const __half* __restrict__ Abase, long long Astride,
    const float* __restrict__ Wbase, long long Wstride,
    __half* __restrict__ Cbase, long long Cstride,
    const float* __restrict__ biasBase, int biasStride,
    int M, int N, int K, int doRelu)
{
    __shared__ uint32_t As[128][36];   // [m][k] tf32
    __shared__ uint32_t Bs[32][136];   // [k][n] tf32

    const int t = blockIdx.z;
    const __half* A = Abase + (long long)t * Astride;
    const float*  W = Wbase + (long long)t * Wstride;
    __half*       C = Cbase + (long long)t * Cstride;

    const int tid  = threadIdx.x;
    const int wid  = tid >> 5;
    const int lane = tid & 31;
    const int gid  = lane >> 2;
    const int tig  = lane & 3;
    const int wm0  = (wid & 1) * 64;
    const int wn0  = (wid >> 1) * 32;
    const int bm0  = blockIdx.y * 128;
    const int bn0  = blockIdx.x * 128;

    float acc[4][4][4];
#pragma unroll
    for (int i = 0; i < 4; i++)
#pragma unroll
        for (int j = 0; j < 4; j++)
#pragma unroll
            for (int q = 0; q < 4; q++) acc[i][j][q] = 0.0f;

    const int nch = K >> 5;
    for (int c = 0; c < nch; c++) {
        // A tile: 128 x 32 halves -> tf32
#pragma unroll
        for (int it = 0; it < 2; it++) {
            int idx = tid + it * 256;              // 0..511, 8 halves each
            int r = idx >> 2, c8 = idx & 3;
            const __half* ap = A + (long long)(bm0 + r) * K + (c << 5) + c8 * 8;
            uint4 v = *(const uint4*)ap;
            const uint32_t* pw = &v.x;
#pragma unroll
            for (int q = 0; q < 4; q++) {
                float2 f = __half22float2(*(const __half2*)&pw[q]);
                As[r][c8 * 8 + q * 2]     = f2tf32(f.x);
                As[r][c8 * 8 + q * 2 + 1] = f2tf32(f.y);
            }
        }
        // B tile: 32 x 128 floats -> tf32
#pragma unroll
        for (int it = 0; it < 4; it++) {
            int idx = tid + it * 256;
            int k = idx >> 5, n4 = idx & 31;
            float4 v = *(const float4*)(W + (long long)((c << 5) + k) * N + bn0 + n4 * 4);
            uint4 o = make_uint4(f2tf32(v.x), f2tf32(v.y), f2tf32(v.z), f2tf32(v.w));
            *(uint4*)&Bs[k][n4 * 4] = o;
        }
        __syncthreads();

#pragma unroll
        for (int ks = 0; ks < 4; ks++) {
            int kk = ks * 8;
            uint32_t bf[4][2];
#pragma unroll
            for (int nf = 0; nf < 4; nf++) {
                bf[nf][0] = Bs[kk + tig][wn0 + nf * 8 + gid];
                bf[nf][1] = Bs[kk + tig + 4][wn0 + nf * 8 + gid];
            }
#pragma unroll
            for (int mf = 0; mf < 4; mf++) {
                int r = wm0 + mf * 16 + gid;
                uint32_t a0 = As[r][kk + tig];
                uint32_t a1 = As[r + 8][kk + tig];
                uint32_t a2 = As[r][kk + tig + 4];
                uint32_t a3 = As[r + 8][kk + tig + 4];
#pragma unroll
                for (int nf = 0; nf < 4; nf++)
                    mma_tf32(acc[mf][nf], a0, a1, a2, a3, bf[nf][0], bf[nf][1]);
            }
        }
        __syncthreads();
    }

    // epilogue: bias + relu, __half2 stores
#pragma unroll
    for (int mf = 0; mf < 4; mf++) {
        int row = bm0 + wm0 + mf * 16 + gid;
#pragma unroll
        for (int nf = 0; nf < 4; nf++) {
            int col = bn0 + wn0 + nf * 8 + tig * 2;
            float b0 = 0.0f, b1 = 0.0f;
            if (biasBase) {
                const float* bp = biasBase + (long long)t * biasStride + col;
                b0 = bp[0]; b1 = bp[1];
            }
            float o0 = acc[mf][nf][0] + b0;
            float o1 = acc[mf][nf][1] + b1;
            float o2 = acc[mf][nf][2] + b0;
            float o3 = acc[mf][nf][3] + b1;
            if (doRelu) {
                o0 = fmaxf(o0, 0.f); o1 = fmaxf(o1, 0.f);
                o2 = fmaxf(o2, 0.f); o3 = fmaxf(o3, 0.f);
            }
            *(__half2*)(C + (long long)row * N + col)       = __floats2half2_rn(o0, o1);
            *(__half2*)(C + (long long)(row + 8) * N + col) = __floats2half2_rn(o2, o3);
        }
    }
}

// ---------------- layer-2 gather: all 3 types fused (R8 config), + output permutation ---------
__global__ void gather2_kernel(const float* __restrict__ b2, float* __restrict__ out) {
    int lane = threadIdx.x & 31;
    int v    = blockIdx.x * 8 + (threadIdx.x >> 5);

    const uint2* __restrict__ h2a = (const uint2*)(g_h2);
    const uint2* __restrict__ h2b = (const uint2*)(g_h2 + (long long)N_NODES * D2);
    const uint2* __restrict__ h2c = (const uint2*)(g_h2 + 2LL * N_NODES * D2);
    int beg = g_rowptr[v];
    int end = g_rowptr[v + 1];

    float4 a0 = make_float4(0.f, 0.f, 0.f, 0.f);
    float4 a1 = make_float4(0.f, 0.f, 0.f, 0.f);
    float4 a2 = make_float4(0.f, 0.f, 0.f, 0.f);

    for (int j = beg; j < end; j++) {
        float4 m = __ldg(&g_meta[j]);
        int src = __float_as_int(m.w);
        uint2 r0 = h2a[src * 32 + lane];
        uint2 r1 = h2b[src * 32 + lane];
        uint2 r2 = h2c[src * 32 + lane];
        float2 f00 = uph2(r0.x), f01 = uph2(r0.y);
        float2 f10 = uph2(r1.x), f11 = uph2(r1.y);
        float2 f20 = uph2(r2.x), f21 = uph2(r2.y);
        a0.x = fmaf(m.x, f00.x, a0.x); a0.y = fmaf(m.x, f00.y, a0.y);
        a0.z = fmaf(m.x, f01.x, a0.z); a0.w = fmaf(m.x, f01.y, a0.w);
        a1.x = fmaf(m.y, f10.x, a1.x); a1.y = fmaf(m.y, f10.y, a1.y);
        a1.z = fmaf(m.y, f11.x, a1.z); a1.w = fmaf(m.y, f11.y, a1.w);
        a2.x = fmaf(m.z, f20.x, a2.x); a2.y = fmaf(m.z, f20.y, a2.y);
        a2.z = fmaf(m.z, f21.x, a2.z); a2.w = fmaf(m.z, f21.y, a2.w);
    }

    float i0 = g_dis[0 * N_NODES + v]; i0 *= i0;
    float i1 = g_dis[1 * N_NODES + v]; i1 *= i1;
    float i2 = g_dis[2 * N_NODES + v]; i2 *= i2;
    uint2 sr0 = h2a[v * 32 + lane];
    uint2 sr1 = h2b[v * 32 + lane];
    uint2 sr2 = h2c[v * 32 + lane];
    float2 s00 = uph2(sr0.x), s01 = uph2(sr0.y);
    float2 s10 = uph2(sr1.x), s11 = uph2(sr1.y);
    float2 s20 = uph2(sr2.x), s21 = uph2(sr2.y);
    float4 bb0 = ((const float4*)(b2 + 0 * D2))[lane];
    float4 bb1 = ((const float4*)(b2 + 1 * D2))[lane];
    float4 bb2 = ((const float4*)(b2 + 2 * D2))[lane];

    a0.x = fmaxf(fmaf(i0, s00.x, a0.x) + bb0.x, 0.f);
    a0.y = fmaxf(fmaf(i0, s00.y, a0.y) + bb0.y, 0.f);
    a0.z = fmaxf(fmaf(i0, s01.x, a0.z) + bb0.z, 0.f);
    a0.w = fmaxf(fmaf(i0, s01.y, a0.w) + bb0.w, 0.f);
    a1.x = fmaxf(fmaf(i1, s10.x, a1.x) + bb1.x, 0.f);
    a1.y = fmaxf(fmaf(i1, s10.y, a1.y) + bb1.y, 0.f);
    a1.z = fmaxf(fmaf(i1, s11.x, a1.z) + bb1.z, 0.f);
    a1.w = fmaxf(fmaf(i1, s11.y, a1.w) + bb1.w, 0.f);
    a2.x = fmaxf(fmaf(i2, s20.x, a2.x) + bb2.x, 0.f);
    a2.y = fmaxf(fmaf(i2, s20.y, a2.y) + bb2.y, 0.f);
    a2.z = fmaxf(fmaf(i2, s21.x, a2.z) + bb2.z, 0.f);
    a2.w = fmaxf(fmaf(i2, s21.y, a2.w) + bb2.w, 0.f);

    int bt = v >> 13;
    int sq = (v >> 9) & 15;
    int vv = v & 511;
    int orow = bt * NNG + vv;
    long long base = ((long long)(orow * SEQ + sq)) * (NT * D2) + lane * 4;
    *(float4*)(out + base)          = a0;
    *(float4*)(out + base + D2)     = a1;
    *(float4*)(out + base + 2 * D2) = a2;
}

// ---------------- launch ----------------
extern "C" void kernel_launch(void* const* d_in, const int* in_sizes, int n_in,
                              void* d_out, int out_size) {
    const float* x  = (const float*)d_in[0];
    const float* ea = (const float*)d_in[1];
    const float* W1 = (const float*)d_in[2];
    const float* b1 = (const float*)d_in[3];
    const float* W2 = (const float*)d_in[4];
    const float* b2 = (const float*)d_in[5];
    const int*   ei = (const int*)d_in[6];
    float* out = (float*)d_out;

    __half *agg, *h1r, *h2;
    cudaGetSymbolAddress((void**)&agg, g_agg);
    cudaGetSymbolAddress((void**)&h1r, g_h1r);
    cudaGetSymbolAddress((void**)&h2,  g_h2);

    zero_kernel  <<<384, 256>>>();
    prep1_kernel <<<E_EDGES / 256 + 128, 256>>>(x, ei, ea);   // hist + stats
    prep2_kernel <<<2, 1024>>>();                              // scan + finstats
    prep3_kernel <<<4096 + 384, 256>>>(x);                     // xnorm + dis
    fill_kernel  <<<E_EDGES / 256, 256>>>(ei, ea);
    gather0_kernel<<<N_NODES / 8, 256>>>();

    // h1r_t = relu(agg_t @ W1_t + b1_t)   [32768,128]@[128,256] -> fp16
    gemm_mma<<<dim3(D1 / 128, N_NODES / 128, NT), 256>>>(
        agg, (long long)N_NODES * F_IN, W1, (long long)F_IN * D1,
        h1r, (long long)N_NODES * D1, b1, D1,
        N_NODES, D1, F_IN, 1);

    // h2_t = h1r_t @ W2_t   [32768,256]@[256,128] -> fp16
    gemm_mma<<<dim3(D2 / 128, N_NODES / 128, NT), 256>>>(
        h1r, (long long)N_NODES * D1, W2, (long long)D1 * D2,
        h2, (long long)N_NODES * D2, (const float*)nullptr, 0,
        N_NODES, D2, D1, 0);

    gather2_kernel<<<N_NODES / 8, 256>>>(b2, out);
}

// round 12
// speedup vs baseline: 1.1051x; 1.0062x over previous
#include <cuda_runtime.h>
#include <cuda_fp16.h>
#include <math.h>
#include <stdint.h>

// Problem constants (fixed by setup_inputs)
#define N_NODES 32768
#define E_EDGES 524288
#define F_IN    128
#define D1      256
#define D2      128
#define NT      3
#define SEQ     16
#define NNG     512

// ---------------- scratch (device globals; no allocation allowed) ----------------
__device__ __half g_xh  [N_NODES * F_IN];            // 8 MB normalized x, fp16
__device__ __half g_agg [NT * N_NODES * F_IN];       // 24 MB aggregated xn, fp16
__device__ __half g_h1r [NT * N_NODES * D1];         // 48 MB relu(agg@W1+b1), fp16
__device__ __half g_h2  [NT * N_NODES * D2];         // 24 MB h1r@W2, fp16
__device__ float  g_deg [NT * N_NODES];
__device__ float  g_dis [NT * N_NODES];
__device__ int    g_counts[N_NODES];
__device__ int    g_rowptr[N_NODES + 1];
__device__ int    g_cursor[N_NODES];
__device__ float4 g_meta[E_EDGES];                   // {w0,w1,w2,src-as-float} CSR by dst
__device__ float  g_colsum[F_IN];
__device__ float  g_colsq [F_IN];
__device__ float  g_mean[F_IN];
__device__ float  g_rstd[F_IN];

// ---------------- helpers ----------------
__device__ __forceinline__ uint32_t f2tf32(float f) {
    uint32_t r;
    asm("cvt.rna.tf32.f32 %0, %1;" : "=r"(r) : "f"(f));
    return r;
}
__device__ __forceinline__ void mma_tf32(float* c,
    uint32_t a0, uint32_t a1, uint32_t a2, uint32_t a3,
    uint32_t b0, uint32_t b1)
{
    asm volatile(
        "mma.sync.aligned.m16n8k8.row.col.f32.tf32.tf32.f32 "
        "{%0,%1,%2,%3}, {%4,%5,%6,%7}, {%8,%9}, {%0,%1,%2,%3};"
        : "+f"(c[0]), "+f"(c[1]), "+f"(c[2]), "+f"(c[3])
        : "r"(a0), "r"(a1), "r"(a2), "r"(a3), "r"(b0), "r"(b1));
}
__device__ __forceinline__ uint32_t pack_h2(float a, float b) {
    __half2 h = __floats2half2_rn(a, b);
    return *(uint32_t*)&h;
}
__device__ __forceinline__ float2 uph2(uint32_t u) {
    return __half22float2(*(__half2*)&u);
}

// ---------------- prep kernels (merged, role-split grids) ----------------
__global__ void zero_kernel() {
    int i = blockIdx.x * 256 + threadIdx.x;
    if (i < N_NODES)      g_counts[i] = 0;
    if (i < NT * N_NODES) g_deg[i] = 0.0f;
    if (i < F_IN) { g_colsum[i] = 0.0f; g_colsq[i] = 0.0f; }
}

// prep1: blocks [0,2048) = edge histogram + weighted degree; blocks [2048,2176) = x column stats
__global__ void prep1_kernel(const float* __restrict__ x,
                             const int* __restrict__ ei, const float* __restrict__ ea) {
    int bid = blockIdx.x;
    if (bid < E_EDGES / 256) {
        int e = bid * 256 + threadIdx.x;
        int dst = ei[E_EDGES + e];
        atomicAdd(&g_counts[dst], 1);
        atomicAdd(&g_deg[0 * N_NODES + dst], fabsf(ea[3 * e + 0]));
        atomicAdd(&g_deg[1 * N_NODES + dst], fabsf(ea[3 * e + 1]));
        atomicAdd(&g_deg[2 * N_NODES + dst], fabsf(ea[3 * e + 2]));
    } else {
        int sbid = bid - E_EDGES / 256;              // 0..127
        int c    = threadIdx.x & 127;
        int half = threadIdx.x >> 7;
        int r0   = sbid * 256 + half * 128;
        float s = 0.0f, q = 0.0f;
        for (int r = 0; r < 128; r++) {
            float v = x[(r0 + r) * F_IN + c];
            s += v; q += v * v;
        }
        atomicAdd(&g_colsum[c], s);
        atomicAdd(&g_colsq[c],  q);
    }
}

// prep2: block 0 = exclusive scan of counts; block 1 = finalize mean/rstd;
//        blocks [2, 98) = dis = rsqrt(deg+1)
__global__ void prep2_kernel() {
    if (blockIdx.x == 0) {
        __shared__ int sums[1024];
        int tid  = threadIdx.x;
        int base = tid * 32;
        int vals[32];
        int s = 0;
#pragma unroll
        for (int i = 0; i < 32; i++) { int v = g_counts[base + i]; vals[i] = s; s += v; }
        sums[tid] = s;
        __syncthreads();
        for (int off = 1; off < 1024; off <<= 1) {
            int v = (tid >= off) ? sums[tid - off] : 0;
            __syncthreads();
            sums[tid] += v;
            __syncthreads();
        }
        int ex = (tid > 0) ? sums[tid - 1] : 0;
#pragma unroll
        for (int i = 0; i < 32; i++) {
            int p = ex + vals[i];
            g_rowptr[base + i] = p;
            g_cursor[base + i] = p;
        }
        if (tid == 1023) g_rowptr[N_NODES] = sums[1023];
    } else if (blockIdx.x == 1) {
        if (threadIdx.x < F_IN) {
            int c = threadIdx.x;
            float n = (float)N_NODES;
            float mean = g_colsum[c] / n;
            float var  = (g_colsq[c] - n * mean * mean) / (n - 1.0f);  // ddof=1
            g_mean[c] = mean;
            g_rstd[c] = rsqrtf(var);
        }
    } else {
        int i = (blockIdx.x - 2) * 1024 + threadIdx.x;
        if (i < NT * N_NODES) g_dis[i] = rsqrtf(g_deg[i] + 1.0f);
    }
}

// prep3: blocks [0,4096) = normalize x -> fp16; blocks [4096,6144) = CSR fill
__global__ void prep3_kernel(const float* __restrict__ x,
                             const int* __restrict__ ei, const float* __restrict__ ea) {
    int bid = blockIdx.x;
    if (bid < 4096) {
        int i  = bid * 256 + threadIdx.x;  // float4 index
        int c4 = (i & 31) * 4;
        float4 v = ((const float4*)x)[i];
        v.x = (v.x - g_mean[c4 + 0]) * g_rstd[c4 + 0];
        v.y = (v.y - g_mean[c4 + 1]) * g_rstd[c4 + 1];
        v.z = (v.z - g_mean[c4 + 2]) * g_rstd[c4 + 2];
        v.w = (v.w - g_mean[c4 + 3]) * g_rstd[c4 + 3];
        ((uint2*)g_xh)[i] = make_uint2(pack_h2(v.x, v.y), pack_h2(v.z, v.w));
    } else {
        int e = (bid - 4096) * 256 + threadIdx.x;
        int src = ei[e];
        int dst = ei[E_EDGES + e];
        int pos = atomicAdd(&g_cursor[dst], 1);
        float4 m;
        m.x = g_dis[0 * N_NODES + src] * fabsf(ea[3 * e + 0]) * g_dis[0 * N_NODES + dst];
        m.y = g_dis[1 * N_NODES + src] * fabsf(ea[3 * e + 1]) * g_dis[1 * N_NODES + dst];
        m.z = g_dis[2 * N_NODES + src] * fabsf(ea[3 * e + 2]) * g_dis[2 * N_NODES + dst];
        m.w = __int_as_float(src);
        g_meta[pos] = m;
    }
}

// ---------------- fused 3-type aggregation of fp16 xn (1 warp/node, R8 config) ----------------
__global__ void gather0_kernel() {
    int lane = threadIdx.x & 31;
    int v    = blockIdx.x * 8 + (threadIdx.x >> 5);

    const uint2* __restrict__ xh = (const uint2*)g_xh;   // 32 uint2 per row (128 halves)
    int beg = g_rowptr[v];
    int end = g_rowptr[v + 1];

    float4 a0 = make_float4(0.f, 0.f, 0.f, 0.f);
    float4 a1 = make_float4(0.f, 0.f, 0.f, 0.f);
    float4 a2 = make_float4(0.f, 0.f, 0.f, 0.f);

    int j = beg;
    for (; j + 1 < end; j += 2) {
        float4 mA = __ldg(&g_meta[j]);
        float4 mB = __ldg(&g_meta[j + 1]);
        uint2 rA = xh[__float_as_int(mA.w) * 32 + lane];
        uint2 rB = xh[__float_as_int(mB.w) * 32 + lane];
        float2 fA0 = uph2(rA.x), fA1 = uph2(rA.y);
        float2 fB0 = uph2(rB.x), fB1 = uph2(rB.y);
        a0.x = fmaf(mA.x, fA0.x, a0.x); a0.y = fmaf(mA.x, fA0.y, a0.y);
        a0.z = fmaf(mA.x, fA1.x, a0.z); a0.w = fmaf(mA.x, fA1.y, a0.w);
        a1.x = fmaf(mA.y, fA0.x, a1.x); a1.y = fmaf(mA.y, fA0.y, a1.y);
        a1.z = fmaf(mA.y, fA1.x, a1.z); a1.w = fmaf(mA.y, fA1.y, a1.w);
        a2.x = fmaf(mA.z, fA0.x, a2.x); a2.y = fmaf(mA.z, fA0.y, a2.y);
        a2.z = fmaf(mA.z, fA1.x, a2.z); a2.w = fmaf(mA.z, fA1.y, a2.w);
        a0.x = fmaf(mB.x, fB0.x, a0.x); a0.y = fmaf(mB.x, fB0.y, a0.y);
        a0.z = fmaf(mB.x, fB1.x, a0.z); a0.w = fmaf(mB.x, fB1.y, a0.w);
        a1.x = fmaf(mB.y, fB0.x, a1.x); a1.y = fmaf(mB.y, fB0.y, a1.y);
        a1.z = fmaf(mB.y, fB1.x, a1.z); a1.w = fmaf(mB.y, fB1.y, a1.w);
        a2.x = fmaf(mB.z, fB0.x, a2.x); a2.y = fmaf(mB.z, fB0.y, a2.y);
        a2.z = fmaf(mB.z, fB1.x, a2.z); a2.w = fmaf(mB.z, fB1.y, a2.w);
    }
    if (j < end) {
        float4 m = __ldg(&g_meta[j]);
        uint2 r = xh[__float_as_int(m.w) * 32 + lane];
        float2 f0 = uph2(r.x), f1 = uph2(r.y);
        a0.x = fmaf(m.x, f0.x, a0.x); a0.y = fmaf(m.x, f0.y, a0.y);
        a0.z = fmaf(m.x, f1.x, a0.z); a0.w = fmaf(m.x, f1.y, a0.w);
        a1.x = fmaf(m.y, f0.x, a1.x); a1.y = fmaf(m.y, f0.y, a1.y);
        a1.z = fmaf(m.y, f1.x, a1.z); a1.w = fmaf(m.y, f1.y, a1.w);
        a2.x = fmaf(m.z, f0.x, a2.x); a2.y = fmaf(m.z, f0.y, a2.y);
        a2.z = fmaf(m.z, f1.x, a2.z); a2.w = fmaf(m.z, f1.y, a2.w);
    }

    uint2 rv = xh[v * 32 + lane];
    float2 v0 = uph2(rv.x), v1 = uph2(rv.y);
    float i0 = g_dis[0 * N_NODES + v]; i0 *= i0;
    float i1 = g_dis[1 * N_NODES + v]; i1 *= i1;
    float i2 = g_dis[2 * N_NODES + v]; i2 *= i2;
    a0.x = fmaf(i0, v0.x, a0.x); a0.y = fmaf(i0, v0.y, a0.y);
    a0.z = fmaf(i0, v1.x, a0.z); a0.w = fmaf(i0, v1.y, a0.w);
    a1.x = fmaf(i1, v0.x, a1.x); a1.y = fmaf(i1, v0.y, a1.y);
    a1.z = fmaf(i1, v1.x, a1.z); a1.w = fmaf(i1, v1.y, a1.w);
    a2.x = fmaf(i2, v0.x, a2.x); a2.y = fmaf(i2, v0.y, a2.y);
    a2.z = fmaf(i2, v1.x, a2.z); a2.w = fmaf(i2, v1.y, a2.w);

    uint2* o = (uint2*)g_agg;
    o[(0 * N_NODES + v) * 32 + lane] = make_uint2(pack_h2(a0.x, a0.y), pack_h2(a0.z, a0.w));
    o[(1 * N_NODES + v) * 32 + lane] = make_uint2(pack_h2(a1.x, a1.y), pack_h2(a1.z, a1.w));
    o[(2 * N_NODES + v) * 32 + lane] = make_uint2(pack_h2(a2.x, a2.y), pack_h2(a2.z, a2.w));
}

// ---------------- tf32 mma.sync GEMM (R8 version, unchanged) ----------------
// C[M,N](fp16) = A(fp16)[M,K] @ W(fp32)[K,N]. Block 128x128, 8 warps, warp tile 64x32, K chunk 32.
__global__ void __launch_bounds__(256) gemm_mma(
    const __half* __restrict__ Abase, long long Astride,
    const float* __restrict__ Wbase, long long Wstride,
    __half* __restrict__ Cbase, long long Cstride,
    const float* __restrict__ biasBase, int biasStride,
    int M, int N, int K, int doRelu)
{
    __shared__ uint32_t As[128][36];   // [m][k] tf32
    __shared__ uint32_t Bs[32][136];   // [k][n] tf32

    const int t = blockIdx.z;
    const __half* A = Abase + (long long)t * Astride;
    const float*  W = Wbase + (long long)t * Wstride;
    __half*       C = Cbase + (long long)t * Cstride;

    const int tid  = threadIdx.x;
    const int wid  = tid >> 5;
    const int lane = tid & 31;
    const int gid  = lane >> 2;
    const int tig  = lane & 3;
    const int wm0  = (wid & 1) * 64;
    const int wn0  = (wid >> 1) * 32;
    const int bm0  = blockIdx.y * 128;
    const int bn0  = blockIdx.x * 128;

    float acc[4][4][4];
#pragma unroll
    for (int i = 0; i < 4; i++)
#pragma unroll
        for (int j = 0; j < 4; j++)
#pragma unroll
            for (int q = 0; q < 4; q++) acc[i][j][q] = 0.0f;

    const int nch = K >> 5;
    for (int c = 0; c < nch; c++) {
        // A tile: 128 x 32 halves -> tf32
#pragma unroll
        for (int it = 0; it < 2; it++) {
            int idx = tid + it * 256;              // 0..511, 8 halves each
            int r = idx >> 2, c8 = idx & 3;
            const __half* ap = A + (long long)(bm0 + r) * K + (c << 5) + c8 * 8;
            uint4 v = *(const uint4*)ap;
            const uint32_t* pw = &v.x;
#pragma unroll
            for (int q = 0; q < 4; q++) {
                float2 f = __half22float2(*(const __half2*)&pw[q]);
                As[r][c8 * 8 + q * 2]     = f2tf32(f.x);
                As[r][c8 * 8 + q * 2 + 1] = f2tf32(f.y);
            }
        }
        // B tile: 32 x 128 floats -> tf32
#pragma unroll
        for (int it = 0; it < 4; it++) {
            int idx = tid + it * 256;
            int k = idx >> 5, n4 = idx & 31;
            float4 v = *(const float4*)(W + (long long)((c << 5) + k) * N + bn0 + n4 * 4);
            uint4 o = make_uint4(f2tf32(v.x), f2tf32(v.y), f2tf32(v.z), f2tf32(v.w));
            *(uint4*)&Bs[k][n4 * 4] = o;
        }
        __syncthreads();

#pragma unroll
        for (int ks = 0; ks < 4; ks++) {
            int kk = ks * 8;
            uint32_t bf[4][2];
#pragma unroll
            for (int nf = 0; nf < 4; nf++) {
                bf[nf][0] = Bs[kk + tig][wn0 + nf * 8 + gid];
                bf[nf][1] = Bs[kk + tig + 4][wn0 + nf * 8 + gid];
            }
#pragma unroll
            for (int mf = 0; mf < 4; mf++) {
                int r = wm0 + mf * 16 + gid;
                uint32_t a0 = As[r][kk + tig];
                uint32_t a1 = As[r + 8][kk + tig];
                uint32_t a2 = As[r][kk + tig + 4];
                uint32_t a3 = As[r + 8][kk + tig + 4];
#pragma unroll
                for (int nf = 0; nf < 4; nf++)
                    mma_tf32(acc[mf][nf], a0, a1, a2, a3, bf[nf][0], bf[nf][1]);
            }
        }
        __syncthreads();
    }

    // epilogue: bias + relu, __half2 stores
#pragma unroll
    for (int mf = 0; mf < 4; mf++) {
        int row = bm0 + wm0 + mf * 16 + gid;
#pragma unroll
        for (int nf = 0; nf < 4; nf++) {
            int col = bn0 + wn0 + nf * 8 + tig * 2;
            float b0 = 0.0f, b1 = 0.0f;
            if (biasBase) {
                const float* bp = biasBase + (long long)t * biasStride + col;
                b0 = bp[0]; b1 = bp[1];
            }
            float o0 = acc[mf][nf][0] + b0;
            float o1 = acc[mf][nf][1] + b1;
            float o2 = acc[mf][nf][2] + b0;
            float o3 = acc[mf][nf][3] + b1;
            if (doRelu) {
                o0 = fmaxf(o0, 0.f); o1 = fmaxf(o1, 0.f);
                o2 = fmaxf(o2, 0.f); o3 = fmaxf(o3, 0.f);
            }
            *(__half2*)(C + (long long)row * N + col)       = __floats2half2_rn(o0, o1);
            *(__half2*)(C + (long long)(row + 8) * N + col) = __floats2half2_rn(o2, o3);
        }
    }
}

// ---------------- layer-2 gather: 3 types fused, 2-edge unroll, + output permutation ---------
__global__ void gather2_kernel(const float* __restrict__ b2, float* __restrict__ out) {
    int lane = threadIdx.x & 31;
    int v    = blockIdx.x * 8 + (threadIdx.x >> 5);

    const uint2* __restrict__ h2a = (const uint2*)(g_h2);
    const uint2* __restrict__ h2b = (const uint2*)(g_h2 + (long long)N_NODES * D2);
    const uint2* __restrict__ h2c = (const uint2*)(g_h2 + 2LL * N_NODES * D2);
    int beg = g_rowptr[v];
    int end = g_rowptr[v + 1];

    float4 a0 = make_float4(0.f, 0.f, 0.f, 0.f);
    float4 a1 = make_float4(0.f, 0.f, 0.f, 0.f);
    float4 a2 = make_float4(0.f, 0.f, 0.f, 0.f);

    int j = beg;
    for (; j + 1 < end; j += 2) {
        float4 mA = __ldg(&g_meta[j]);
        float4 mB = __ldg(&g_meta[j + 1]);
        int sA = __float_as_int(mA.w) * 32 + lane;
        int sB = __float_as_int(mB.w) * 32 + lane;
        uint2 rA0 = h2a[sA], rA1 = h2b[sA], rA2 = h2c[sA];
        uint2 rB0 = h2a[sB], rB1 = h2b[sB], rB2 = h2c[sB];
        float2 fA00 = uph2(rA0.x), fA01 = uph2(rA0.y);
        float2 fA10 = uph2(rA1.x), fA11 = uph2(rA1.y);
        float2 fA20 = uph2(rA2.x), fA21 = uph2(rA2.y);
        float2 fB00 = uph2(rB0.x), fB01 = uph2(rB0.y);
        float2 fB10 = uph2(rB1.x), fB11 = uph2(rB1.y);
        float2 fB20 = uph2(rB2.x), fB21 = uph2(rB2.y);
        a0.x = fmaf(mA.x, fA00.x, a0.x); a0.y = fmaf(mA.x, fA00.y, a0.y);
        a0.z = fmaf(mA.x, fA01.x, a0.z); a0.w = fmaf(mA.x, fA01.y, a0.w);
        a1.x = fmaf(mA.y, fA10.x, a1.x); a1.y = fmaf(mA.y, fA10.y, a1.y);
        a1.z = fmaf(mA.y, fA11.x, a1.z); a1.w = fmaf(mA.y, fA11.y, a1.w);
        a2.x = fmaf(mA.z, fA20.x, a2.x); a2.y = fmaf(mA.z, fA20.y, a2.y);
        a2.z = fmaf(mA.z, fA21.x, a2.z); a2.w = fmaf(mA.z, fA21.y, a2.w);
        a0.x = fmaf(mB.x, fB00.x, a0.x); a0.y = fmaf(mB.x, fB00.y, a0.y);
        a0.z = fmaf(mB.x, fB01.x, a0.z); a0.w = fmaf(mB.x, fB01.y, a0.w);
        a1.x = fmaf(mB.y, fB10.x, a1.x); a1.y = fmaf(mB.y, fB10.y, a1.y);
        a1.z = fmaf(mB.y, fB11.x, a1.z); a1.w = fmaf(mB.y, fB11.y, a1.w);
        a2.x = fmaf(mB.z, fB20.x, a2.x); a2.y = fmaf(mB.z, fB20.y, a2.y);
        a2.z = fmaf(mB.z, fB21.x, a2.z); a2.w = fmaf(mB.z, fB21.y, a2.w);
    }
    if (j < end) {
        float4 m = __ldg(&g_meta[j]);
        int s = __float_as_int(m.w) * 32 + lane;
        uint2 r0 = h2a[s], r1 = h2b[s], r2 = h2c[s];
        float2 f00 = uph2(r0.x), f01 = uph2(r0.y);
        float2 f10 = uph2(r1.x), f11 = uph2(r1.y);
        float2 f20 = uph2(r2.x), f21 = uph2(r2.y);
        a0.x = fmaf(m.x, f00.x, a0.x); a0.y = fmaf(m.x, f00.y, a0.y);
        a0.z = fmaf(m.x, f01.x, a0.z); a0.w = fmaf(m.x, f01.y, a0.w);
        a1.x = fmaf(m.y, f10.x, a1.x); a1.y = fmaf(m.y, f10.y, a1.y);
        a1.z = fmaf(m.y, f11.x, a1.z); a1.w = fmaf(m.y, f11.y, a1.w);
        a2.x = fmaf(m.z, f20.x, a2.x); a2.y = fmaf(m.z, f20.y, a2.y);
        a2.z = fmaf(m.z, f21.x, a2.z); a2.w = fmaf(m.z, f21.y, a2.w);
    }

    float i0 = g_dis[0 * N_NODES + v]; i0 *= i0;
    float i1 = g_dis[1 * N_NODES + v]; i1 *= i1;
    float i2 = g_dis[2 * N_NODES + v]; i2 *= i2;
    uint2 sr0 = h2a[v * 32 + lane];
    uint2 sr1 = h2b[v * 32 + lane];
    uint2 sr2 = h2c[v * 32 + lane];
    float2 s00 = uph2(sr0.x), s01 = uph2(sr0.y);
    float2 s10 = uph2(sr1.x), s11 = uph2(sr1.y);
    float2 s20 = uph2(sr2.x), s21 = uph2(sr2.y);
    float4 bb0 = ((const float4*)(b2 + 0 * D2))[lane];
    float4 bb1 = ((const float4*)(b2 + 1 * D2))[lane];
    float4 bb2 = ((const float4*)(b2 + 2 * D2))[lane];

    a0.x = fmaxf(fmaf(i0, s00.x, a0.x) + bb0.x, 0.f);
    a0.y = fmaxf(fmaf(i0, s00.y, a0.y) + bb0.y, 0.f);
    a0.z = fmaxf(fmaf(i0, s01.x, a0.z) + bb0.z, 0.f);
    a0.w = fmaxf(fmaf(i0, s01.y, a0.w) + bb0.w, 0.f);
    a1.x = fmaxf(fmaf(i1, s10.x, a1.x) + bb1.x, 0.f);
    a1.y = fmaxf(fmaf(i1, s10.y, a1.y) + bb1.y, 0.f);
    a1.z = fmaxf(fmaf(i1, s11.x, a1.z) + bb1.z, 0.f);
    a1.w = fmaxf(fmaf(i1, s11.y, a1.w) + bb1.w, 0.f);
    a2.x = fmaxf(fmaf(i2, s20.x, a2.x) + bb2.x, 0.f);
    a2.y = fmaxf(fmaf(i2, s20.y, a2.y) + bb2.y, 0.f);
    a2.z = fmaxf(fmaf(i2, s21.x, a2.z) + bb2.z, 0.f);
    a2.w = fmaxf(fmaf(i2, s21.y, a2.w) + bb2.w, 0.f);

    int bt = v >> 13;
    int sq = (v >> 9) & 15;
    int vv = v & 511;
    int orow = bt * NNG + vv;
    long long base = ((long long)(orow * SEQ + sq)) * (NT * D2) + lane * 4;
    *(float4*)(out + base)          = a0;
    *(float4*)(out + base + D2)     = a1;
    *(float4*)(out + base + 2 * D2) = a2;
}

// ---------------- launch ----------------
extern "C" void kernel_launch(void* const* d_in, const int* in_sizes, int n_in,
                              void* d_out, int out_size) {
    const float* x  = (const float*)d_in[0];
    const float* ea = (const float*)d_in[1];
    const float* W1 = (const float*)d_in[2];
    const float* b1 = (const float*)d_in[3];
    const float* W2 = (const float*)d_in[4];
    const float* b2 = (const float*)d_in[5];
    const int*   ei = (const int*)d_in[6];
    float* out = (float*)d_out;

    __half *agg, *h1r, *h2;
    cudaGetSymbolAddress((void**)&agg, g_agg);
    cudaGetSymbolAddress((void**)&h1r, g_h1r);
    cudaGetSymbolAddress((void**)&h2,  g_h2);

    zero_kernel  <<<384, 256>>>();
    prep1_kernel <<<E_EDGES / 256 + 128, 256>>>(x, ei, ea);   // hist + stats
    prep2_kernel <<<2 + 96, 1024>>>();                         // scan + finstats + dis
    prep3_kernel <<<4096 + E_EDGES / 256, 256>>>(x, ei, ea);   // xnorm + fill
    gather0_kernel<<<N_NODES / 8, 256>>>();

    // h1r_t = relu(agg_t @ W1_t + b1_t)   [32768,128]@[128,256] -> fp16
    gemm_mma<<<dim3(D1 / 128, N_NODES / 128, NT), 256>>>(
        agg, (long long)N_NODES * F_IN, W1, (long long)F_IN * D1,
        h1r, (long long)N_NODES * D1, b1, D1,
        N_NODES, D1, F_IN, 1);

    // h2_t = h1r_t @ W2_t   [32768,256]@[256,128] -> fp16
    gemm_mma<<<dim3(D2 / 128, N_NODES / 128, NT), 256>>>(
        h1r, (long long)N_NODES * D1, W2, (long long)D1 * D2,
        h2, (long long)N_NODES * D2, (const float*)nullptr, 0,
        N_NODES, D2, D1, 0);

    gather2_kernel<<<N_NODES / 8, 256>>>(b2, out);
}

// round 14
// speedup vs baseline: 1.1924x; 1.0790x over previous
#include <cuda_runtime.h>
#include <cuda_fp16.h>
#include <math.h>
#include <stdint.h>

// Problem constants (fixed by setup_inputs)
#define N_NODES 32768
#define E_EDGES 524288
#define F_IN    128
#define D1      256
#define D2      128
#define NT      3
#define SEQ     16
#define NNG     512

// ---------------- scratch (device globals; no allocation allowed) ----------------
__device__ __half g_xh  [N_NODES * F_IN];            // 8 MB normalized x, fp16
__device__ __half g_agg [NT * N_NODES * F_IN];       // 24 MB aggregated xn, fp16
__device__ __half g_h1r [NT * N_NODES * D1];         // 48 MB relu(agg@W1+b1), fp16
__device__ __half g_h2  [NT * N_NODES * D2];         // 24 MB h1r@W2, fp16, [node][type][128]
__device__ float  g_deg [NT * N_NODES];
__device__ float  g_dis [NT * N_NODES];
__device__ int    g_counts[N_NODES];
__device__ int    g_rowptr[N_NODES + 1];
__device__ int    g_rank[E_EDGES];                   // per-edge rank within dst (from hist)
__device__ float4 g_meta[E_EDGES];                   // {w0,w1,w2,src-as-float} CSR by dst
__device__ float  g_colsum[F_IN];
__device__ float  g_colsq [F_IN];
__device__ float  g_mean[F_IN];
__device__ float  g_rstd[F_IN];

// ---------------- helpers ----------------
__device__ __forceinline__ uint32_t f2tf32(float f) {
    uint32_t r;
    asm("cvt.rna.tf32.f32 %0, %1;" : "=r"(r) : "f"(f));
    return r;
}
__device__ __forceinline__ void mma_tf32(float* c,
    uint32_t a0, uint32_t a1, uint32_t a2, uint32_t a3,
    uint32_t b0, uint32_t b1)
{
    asm volatile(
        "mma.sync.aligned.m16n8k8.row.col.f32.tf32.tf32.f32 "
        "{%0,%1,%2,%3}, {%4,%5,%6,%7}, {%8,%9}, {%0,%1,%2,%3};"
        : "+f"(c[0]), "+f"(c[1]), "+f"(c[2]), "+f"(c[3])
        : "r"(a0), "r"(a1), "r"(a2), "r"(a3), "r"(b0), "r"(b1));
}
__device__ __forceinline__ uint32_t pack_h2(float a, float b) {
    __half2 h = __floats2half2_rn(a, b);
    return *(uint32_t*)&h;
}
__device__ __forceinline__ float2 uph2(uint32_t u) {
    return __half22float2(*(__half2*)&u);
}

// ---------------- prep kernels (merged, role-split grids) ----------------
__global__ void zero_kernel() {
    int i = blockIdx.x * 256 + threadIdx.x;
    if (i < N_NODES)      g_counts[i] = 0;
    if (i < NT * N_NODES) g_deg[i] = 0.0f;
    if (i < F_IN) { g_colsum[i] = 0.0f; g_colsq[i] = 0.0f; }
}

// prep1: blocks [0,2048) = edge histogram (rank-returning) + weighted degree;
//        blocks [2048,2176) = x column stats
__global__ void prep1_kernel(const float* __restrict__ x,
                             const int* __restrict__ ei, const float* __restrict__ ea) {
    int bid = blockIdx.x;
    if (bid < E_EDGES / 256) {
        int e = bid * 256 + threadIdx.x;
        int dst = ei[E_EDGES + e];
        g_rank[e] = atomicAdd(&g_counts[dst], 1);
        atomicAdd(&g_deg[0 * N_NODES + dst], fabsf(ea[3 * e + 0]));
        atomicAdd(&g_deg[1 * N_NODES + dst], fabsf(ea[3 * e + 1]));
        atomicAdd(&g_deg[2 * N_NODES + dst], fabsf(ea[3 * e + 2]));
    } else {
        int sbid = bid - E_EDGES / 256;              // 0..127
        int c    = threadIdx.x & 127;
        int half = threadIdx.x >> 7;
        int r0   = sbid * 256 + half * 128;
        float s = 0.0f, q = 0.0f;
        for (int r = 0; r < 128; r++) {
            float v = x[(r0 + r) * F_IN + c];
            s += v; q += v * v;
        }
        atomicAdd(&g_colsum[c], s);
        atomicAdd(&g_colsq[c],  q);
    }
}

// prep2: block 0 = exclusive scan of counts; block 1 = finalize mean/rstd;
//        blocks [2, 98) = dis = rsqrt(deg+1)
__global__ void prep2_kernel() {
    if (blockIdx.x == 0) {
        __shared__ int sums[1024];
        int tid  = threadIdx.x;
        int base = tid * 32;
        int vals[32];
        int s = 0;
#pragma unroll
        for (int i = 0; i < 32; i++) { int v = g_counts[base + i]; vals[i] = s; s += v; }
        sums[tid] = s;
        __syncthreads();
        for (int off = 1; off < 1024; off <<= 1) {
            int v = (tid >= off) ? sums[tid - off] : 0;
            __syncthreads();
            sums[tid] += v;
            __syncthreads();
        }
        int ex = (tid > 0) ? sums[tid - 1] : 0;
#pragma unroll
        for (int i = 0; i < 32; i++) {
            g_rowptr[base + i] = ex + vals[i];
        }
        if (tid == 1023) g_rowptr[N_NODES] = sums[1023];
    } else if (blockIdx.x == 1) {
        if (threadIdx.x < F_IN) {
            int c = threadIdx.x;
            float n = (float)N_NODES;
            float mean = g_colsum[c] / n;
            float var  = (g_colsq[c] - n * mean * mean) / (n - 1.0f);  // ddof=1
            g_mean[c] = mean;
            g_rstd[c] = rsqrtf(var);
        }
    } else {
        int i = (blockIdx.x - 2) * 1024 + threadIdx.x;
        if (i < NT * N_NODES) g_dis[i] = rsqrtf(g_deg[i] + 1.0f);
    }
}

// prep3: blocks [0,4096) = normalize x -> fp16; blocks [4096,6144) = deterministic CSR fill
__global__ void prep3_kernel(const float* __restrict__ x,
                             const int* __restrict__ ei, const float* __restrict__ ea) {
    int bid = blockIdx.x;
    if (bid < 4096) {
        int i  = bid * 256 + threadIdx.x;  // float4 index
        int c4 = (i & 31) * 4;
        float4 v = ((const float4*)x)[i];
        v.x = (v.x - g_mean[c4 + 0]) * g_rstd[c4 + 0];
        v.y = (v.y - g_mean[c4 + 1]) * g_rstd[c4 + 1];
        v.z = (v.z - g_mean[c4 + 2]) * g_rstd[c4 + 2];
        v.w = (v.w - g_mean[c4 + 3]) * g_rstd[c4 + 3];
        ((uint2*)g_xh)[i] = make_uint2(pack_h2(v.x, v.y), pack_h2(v.z, v.w));
    } else {
        int e = (bid - 4096) * 256 + threadIdx.x;
        int src = ei[e];
        int dst = ei[E_EDGES + e];
        int pos = g_rowptr[dst] + g_rank[e];     // deterministic scatter, no atomic
        float4 m;
        m.x = g_dis[0 * N_NODES + src] * fabsf(ea[3 * e + 0]) * g_dis[0 * N_NODES + dst];
        m.y = g_dis[1 * N_NODES + src] * fabsf(ea[3 * e + 1]) * g_dis[1 * N_NODES + dst];
        m.z = g_dis[2 * N_NODES + src] * fabsf(ea[3 * e + 2]) * g_dis[2 * N_NODES + dst];
        m.w = __int_as_float(src);
        g_meta[pos] = m;
    }
}

// ---------------- fused 3-type aggregation of fp16 xn (1 warp/node, R8 config) ----------------
__global__ void gather0_kernel() {
    int lane = threadIdx.x & 31;
    int v    = blockIdx.x * 8 + (threadIdx.x >> 5);

    const uint2* __restrict__ xh = (const uint2*)g_xh;   // 32 uint2 per row (128 halves)
    int beg = g_rowptr[v];
    int end = g_rowptr[v + 1];

    float4 a0 = make_float4(0.f, 0.f, 0.f, 0.f);
    float4 a1 = make_float4(0.f, 0.f, 0.f, 0.f);
    float4 a2 = make_float4(0.f, 0.f, 0.f, 0.f);

    int j = beg;
    for (; j + 1 < end; j += 2) {
        float4 mA = __ldg(&g_meta[j]);
        float4 mB = __ldg(&g_meta[j + 1]);
        uint2 rA = xh[__float_as_int(mA.w) * 32 + lane];
        uint2 rB = xh[__float_as_int(mB.w) * 32 + lane];
        float2 fA0 = uph2(rA.x), fA1 = uph2(rA.y);
        float2 fB0 = uph2(rB.x), fB1 = uph2(rB.y);
        a0.x = fmaf(mA.x, fA0.x, a0.x); a0.y = fmaf(mA.x, fA0.y, a0.y);
        a0.z = fmaf(mA.x, fA1.x, a0.z); a0.w = fmaf(mA.x, fA1.y, a0.w);
        a1.x = fmaf(mA.y, fA0.x, a1.x); a1.y = fmaf(mA.y, fA0.y, a1.y);
        a1.z = fmaf(mA.y, fA1.x, a1.z); a1.w = fmaf(mA.y, fA1.y, a1.w);
        a2.x = fmaf(mA.z, fA0.x, a2.x); a2.y = fmaf(mA.z, fA0.y, a2.y);
        a2.z = fmaf(mA.z, fA1.x, a2.z); a2.w = fmaf(mA.z, fA1.y, a2.w);
        a0.x = fmaf(mB.x, fB0.x, a0.x); a0.y = fmaf(mB.x, fB0.y, a0.y);
        a0.z = fmaf(mB.x, fB1.x, a0.z); a0.w = fmaf(mB.x, fB1.y, a0.w);
        a1.x = fmaf(mB.y, fB0.x, a1.x); a1.y = fmaf(mB.y, fB0.y, a1.y);
        a1.z = fmaf(mB.y, fB1.x, a1.z); a1.w = fmaf(mB.y, fB1.y, a1.w);
        a2.x = fmaf(mB.z, fB0.x, a2.x); a2.y = fmaf(mB.z, fB0.y, a2.y);
        a2.z = fmaf(mB.z, fB1.x, a2.z); a2.w = fmaf(mB.z, fB1.y, a2.w);
    }
    if (j < end) {
        float4 m = __ldg(&g_meta[j]);
        uint2 r = xh[__float_as_int(m.w) * 32 + lane];
        float2 f0 = uph2(r.x), f1 = uph2(r.y);
        a0.x = fmaf(m.x, f0.x, a0.x); a0.y = fmaf(m.x, f0.y, a0.y);
        a0.z = fmaf(m.x, f1.x, a0.z); a0.w = fmaf(m.x, f1.y, a0.w);
        a1.x = fmaf(m.y, f0.x, a1.x); a1.y = fmaf(m.y, f0.y, a1.y);
        a1.z = fmaf(m.y, f1.x, a1.z); a1.w = fmaf(m.y, f1.y, a1.w);
        a2.x = fmaf(m.z, f0.x, a2.x); a2.y = fmaf(m.z, f0.y, a2.y);
        a2.z = fmaf(m.z, f1.x, a2.z); a2.w = fmaf(m.z, f1.y, a2.w);
    }

    uint2 rv = xh[v * 32 + lane];
    float2 v0 = uph2(rv.x), v1 = uph2(rv.y);
    float i0 = g_dis[0 * N_NODES + v]; i0 *= i0;
    float i1 = g_dis[1 * N_NODES + v]; i1 *= i1;
    float i2 = g_dis[2 * N_NODES + v]; i2 *= i2;
    a0.x = fmaf(i0, v0.x, a0.x); a0.y = fmaf(i0, v0.y, a0.y);
    a0.z = fmaf(i0, v1.x, a0.z); a0.w = fmaf(i0, v1.y, a0.w);
    a1.x = fmaf(i1, v0.x, a1.x); a1.y = fmaf(i1, v0.y, a1.y);
    a1.z = fmaf(i1, v1.x, a1.z); a1.w = fmaf(i1, v1.y, a1.w);
    a2.x = fmaf(i2, v0.x, a2.x); a2.y = fmaf(i2, v0.y, a2.y);
    a2.z = fmaf(i2, v1.x, a2.z); a2.w = fmaf(i2, v1.y, a2.w);

    uint2* o = (uint2*)g_agg;
    o[(0 * N_NODES + v) * 32 + lane] = make_uint2(pack_h2(a0.x, a0.y), pack_h2(a0.z, a0.w));
    o[(1 * N_NODES + v) * 32 + lane] = make_uint2(pack_h2(a1.x, a1.y), pack_h2(a1.z, a1.w));
    o[(2 * N_NODES + v) * 32 + lane] = make_uint2(pack_h2(a2.x, a2.y), pack_h2(a2.z, a2.w));
}

// ---------------- tf32 mma.sync GEMM (R8 inner loop; adds C row-stride) ----------------
// C[M,N](fp16) = A(fp16)[M,K] @ W(fp32)[K,N]. Block 128x128, 8 warps, warp tile 64x32, K chunk 32.
__global__ void __launch_bounds__(256) gemm_mma(
    const __half* __restrict__ Abase, long long Astride,
    const float* __restrict__ Wbase, long long Wstride,
    __half* __restrict__ Cbase, long long Cstride, int Crowstride,
    const float* __restrict__ biasBase, int biasStride,
    int M, int N, int K, int doRelu)
{
    __shared__ uint32_t As[128][36];   // [m][k] tf32
    __shared__ uint32_t Bs[32][136];   // [k][n] tf32

    const int t = blockIdx.z;
    const __half* A = Abase + (long long)t * Astride;
    const float*  W = Wbase + (long long)t * Wstride;
    __half*       C = Cbase + (long long)t * Cstride;

    const int tid  = threadIdx.x;
    const int wid  = tid >> 5;
    const int lane = tid & 31;
    const int gid  = lane >> 2;
    const int tig  = lane & 3;
    const int wm0  = (wid & 1) * 64;
    const int wn0  = (wid >> 1) * 32;
    const int bm0  = blockIdx.y * 128;
    const int bn0  = blockIdx.x * 128;

    float acc[4][4][4];
#pragma unroll
    for (int i = 0; i < 4; i++)
#pragma unroll
        for (int j = 0; j < 4; j++)
#pragma unroll
            for (int q = 0; q < 4; q++) acc[i][j][q] = 0.0f;

    const int nch = K >> 5;
    for (int c = 0; c < nch; c++) {
        // A tile: 128 x 32 halves -> tf32
#pragma unroll
        for (int it = 0; it < 2; it++) {
            int idx = tid + it * 256;              // 0..511, 8 halves each
            int r = idx >> 2, c8 = idx & 3;
            const __half* ap = A + (long long)(bm0 + r) * K + (c << 5) + c8 * 8;
            uint4 v = *(const uint4*)ap;
            const uint32_t* pw = &v.x;
#pragma unroll
            for (int q = 0; q < 4; q++) {
                float2 f = __half22float2(*(const __half2*)&pw[q]);
                As[r][c8 * 8 + q * 2]     = f2tf32(f.x);
                As[r][c8 * 8 + q * 2 + 1] = f2tf32(f.y);
            }
        }
        // B tile: 32 x 128 floats -> tf32
#pragma unroll
        for (int it = 0; it < 4; it++) {
            int idx = tid + it * 256;
            int k = idx >> 5, n4 = idx & 31;
            float4 v = *(const float4*)(W + (long long)((c << 5) + k) * N + bn0 + n4 * 4);
            uint4 o = make_uint4(f2tf32(v.x), f2tf32(v.y), f2tf32(v.z), f2tf32(v.w));
            *(uint4*)&Bs[k][n4 * 4] = o;
        }
        __syncthreads();

#pragma unroll
        for (int ks = 0; ks < 4; ks++) {
            int kk = ks * 8;
            uint32_t bf[4][2];
#pragma unroll
            for (int nf = 0; nf < 4; nf++) {
                bf[nf][0] = Bs[kk + tig][wn0 + nf * 8 + gid];
                bf[nf][1] = Bs[kk + tig + 4][wn0 + nf * 8 + gid];
            }
#pragma unroll
            for (int mf = 0; mf < 4; mf++) {
                int r = wm0 + mf * 16 + gid;
                uint32_t a0 = As[r][kk + tig];
                uint32_t a1 = As[r + 8][kk + tig];
                uint32_t a2 = As[r][kk + tig + 4];
                uint32_t a3 = As[r + 8][kk + tig + 4];
#pragma unroll
                for (int nf = 0; nf < 4; nf++)
                    mma_tf32(acc[mf][nf], a0, a1, a2, a3, bf[nf][0], bf[nf][1]);
            }
        }
        __syncthreads();
    }

    // epilogue: bias + relu, __half2 stores (row stride Crowstride)
#pragma unroll
    for (int mf = 0; mf < 4; mf++) {
        int row = bm0 + wm0 + mf * 16 + gid;
#pragma unroll
        for (int nf = 0; nf < 4; nf++) {
            int col = bn0 + wn0 + nf * 8 + tig * 2;
            float b0 = 0.0f, b1 = 0.0f;
            if (biasBase) {
                const float* bp = biasBase + (long long)t * biasStride + col;
                b0 = bp[0]; b1 = bp[1];
            }
            float o0 = acc[mf][nf][0] + b0;
            float o1 = acc[mf][nf][1] + b1;
            float o2 = acc[mf][nf][2] + b0;
            float o3 = acc[mf][nf][3] + b1;
            if (doRelu) {
                o0 = fmaxf(o0, 0.f); o1 = fmaxf(o1, 0.f);
                o2 = fmaxf(o2, 0.f); o3 = fmaxf(o3, 0.f);
            }
            *(__half2*)(C + (long long)row * Crowstride + col)       = __floats2half2_rn(o0, o1);
            *(__half2*)(C + (long long)(row + 8) * Crowstride + col) = __floats2half2_rn(o2, o3);
        }
    }
}

// ---------------- layer-2 gather: interleaved h2 [node][type][128], 2-edge unroll ------------
__global__ void gather2_kernel(const float* __restrict__ b2, float* __restrict__ out) {
    int lane = threadIdx.x & 31;
    int v    = blockIdx.x * 8 + (threadIdx.x >> 5);

    const uint2* __restrict__ h2 = (const uint2*)g_h2;   // 96 uint2 per node (3 types x 32)
    int beg = g_rowptr[v];
    int end = g_rowptr[v + 1];

    float4 a0 = make_float4(0.f, 0.f, 0.f, 0.f);
    float4 a1 = make_float4(0.f, 0.f, 0.f, 0.f);
    float4 a2 = make_float4(0.f, 0.f, 0.f, 0.f);

    int j = beg;
    for (; j + 1 < end; j += 2) {
        float4 mA = __ldg(&g_meta[j]);
        float4 mB = __ldg(&g_meta[j + 1]);
        int sA = __float_as_int(mA.w) * 96 + lane;
        int sB = __float_as_int(mB.w) * 96 + lane;
        uint2 rA0 = h2[sA], rA1 = h2[sA + 32], rA2 = h2[sA + 64];
        uint2 rB0 = h2[sB], rB1 = h2[sB + 32], rB2 = h2[sB + 64];
        float2 fA00 = uph2(rA0.x), fA01 = uph2(rA0.y);
        float2 fA10 = uph2(rA1.x), fA11 = uph2(rA1.y);
        float2 fA20 = uph2(rA2.x), fA21 = uph2(rA2.y);
        float2 fB00 = uph2(rB0.x), fB01 = uph2(rB0.y);
        float2 fB10 = uph2(rB1.x), fB11 = uph2(rB1.y);
        float2 fB20 = uph2(rB2.x), fB21 = uph2(rB2.y);
        a0.x = fmaf(mA.x, fA00.x, a0.x); a0.y = fmaf(mA.x, fA00.y, a0.y);
        a0.z = fmaf(mA.x, fA01.x, a0.z); a0.w = fmaf(mA.x, fA01.y, a0.w);
        a1.x = fmaf(mA.y, fA10.x, a1.x); a1.y = fmaf(mA.y, fA10.y, a1.y);
        a1.z = fmaf(mA.y, fA11.x, a1.z); a1.w = fmaf(mA.y, fA11.y, a1.w);
        a2.x = fmaf(mA.z, fA20.x, a2.x); a2.y = fmaf(mA.z, fA20.y, a2.y);
        a2.z = fmaf(mA.z, fA21.x, a2.z); a2.w = fmaf(mA.z, fA21.y, a2.w);
        a0.x = fmaf(mB.x, fB00.x, a0.x); a0.y = fmaf(mB.x, fB00.y, a0.y);
        a0.z = fmaf(mB.x, fB01.x, a0.z); a0.w = fmaf(mB.x, fB01.y, a0.w);
        a1.x = fmaf(mB.y, fB10.x, a1.x); a1.y = fmaf(mB.y, fB10.y, a1.y);
        a1.z = fmaf(mB.y, fB11.x, a1.z); a1.w = fmaf(mB.y, fB11.y, a1.w);
        a2.x = fmaf(mB.z, fB20.x, a2.x); a2.y = fmaf(mB.z, fB20.y, a2.y);
        a2.z = fmaf(mB.z, fB21.x, a2.z); a2.w = fmaf(mB.z, fB21.y, a2.w);
    }
    if (j < end) {
        float4 m = __ldg(&g_meta[j]);
        int s = __float_as_int(m.w) * 96 + lane;
        uint2 r0 = h2[s], r1 = h2[s + 32], r2 = h2[s + 64];
        float2 f00 = uph2(r0.x), f01 = uph2(r0.y);
        float2 f10 = uph2(r1.x), f11 = uph2(r1.y);
        float2 f20 = uph2(r2.x), f21 = uph2(r2.y);
        a0.x = fmaf(m.x, f00.x, a0.x); a0.y = fmaf(m.x, f00.y, a0.y);
        a0.z = fmaf(m.x, f01.x, a0.z); a0.w = fmaf(m.x, f01.y, a0.w);
        a1.x = fmaf(m.y, f10.x, a1.x); a1.y = fmaf(m.y, f10.y, a1.y);
        a1.z = fmaf(m.y, f11.x, a1.z); a1.w = fmaf(m.y, f11.y, a1.w);
        a2.x = fmaf(m.z, f20.x, a2.x); a2.y = fmaf(m.z, f20.y, a2.y);
        a2.z = fmaf(m.z, f21.x, a2.z); a2.w = fmaf(m.z, f21.y, a2.w);
    }

    float i0 = g_dis[0 * N_NODES + v]; i0 *= i0;
    float i1 = g_dis[1 * N_NODES + v]; i1 *= i1;
    float i2 = g_dis[2 * N_NODES + v]; i2 *= i2;
    int sv = v * 96 + lane;
    uint2 sr0 = h2[sv], sr1 = h2[sv + 32], sr2 = h2[sv + 64];
    float2 s00 = uph2(sr0.x), s01 = uph2(sr0.y);
    float2 s10 = uph2(sr1.x), s11 = uph2(sr1.y);
    float2 s20 = uph2(sr2.x), s21 = uph2(sr2.y);
    float4 bb0 = ((const float4*)(b2 + 0 * D2))[lane];
    float4 bb1 = ((const float4*)(b2 + 1 * D2))[lane];
    float4 bb2 = ((const float4*)(b2 + 2 * D2))[lane];

    a0.x = fmaxf(fmaf(i0, s00.x, a0.x) + bb0.x, 0.f);
    a0.y = fmaxf(fmaf(i0, s00.y, a0.y) + bb0.y, 0.f);
    a0.z = fmaxf(fmaf(i0, s01.x, a0.z) + bb0.z, 0.f);
    a0.w = fmaxf(fmaf(i0, s01.y, a0.w) + bb0.w, 0.f);
    a1.x = fmaxf(fmaf(i1, s10.x, a1.x) + bb1.x, 0.f);
    a1.y = fmaxf(fmaf(i1, s10.y, a1.y) + bb1.y, 0.f);
    a1.z = fmaxf(fmaf(i1, s11.x, a1.z) + bb1.z, 0.f);
    a1.w = fmaxf(fmaf(i1, s11.y, a1.w) + bb1.w, 0.f);
    a2.x = fmaxf(fmaf(i2, s20.x, a2.x) + bb2.x, 0.f);
    a2.y = fmaxf(fmaf(i2, s20.y, a2.y) + bb2.y, 0.f);
    a2.z = fmaxf(fmaf(i2, s21.x, a2.z) + bb2.z, 0.f);
    a2.w = fmaxf(fmaf(i2, s21.y, a2.w) + bb2.w, 0.f);

    int bt = v >> 13;
    int sq = (v >> 9) & 15;
    int vv = v & 511;
    int orow = bt * NNG + vv;
    long long base = ((long long)(orow * SEQ + sq)) * (NT * D2) + lane * 4;
    *(float4*)(out + base)          = a0;
    *(float4*)(out + base + D2)     = a1;
    *(float4*)(out + base + 2 * D2) = a2;
}

// ---------------- launch ----------------
extern "C" void kernel_launch(void* const* d_in, const int* in_sizes, int n_in,
                              void* d_out, int out_size) {
    const float* x  = (const float*)d_in[0];
    const float* ea = (const float*)d_in[1];
    const float* W1 = (const float*)d_in[2];
    const float* b1 = (const float*)d_in[3];
    const float* W2 = (const float*)d_in[4];
    const float* b2 = (const float*)d_in[5];
    const int*   ei = (const int*)d_in[6];
    float* out = (float*)d_out;

    __half *agg, *h1r, *h2;
    cudaGetSymbolAddress((void**)&agg, g_agg);
    cudaGetSymbolAddress((void**)&h1r, g_h1r);
    cudaGetSymbolAddress((void**)&h2,  g_h2);

    zero_kernel  <<<384, 256>>>();
    prep1_kernel <<<E_EDGES / 256 + 128, 256>>>(x, ei, ea);   // hist(rank) + stats
    prep2_kernel <<<2 + 96, 1024>>>();                         // scan + finstats + dis
    prep3_kernel <<<4096 + E_EDGES / 256, 256>>>(x, ei, ea);   // xnorm + deterministic fill
    gather0_kernel<<<N_NODES / 8, 256>>>();

    // h1r_t = relu(agg_t @ W1_t + b1_t)   [32768,128]@[128,256] -> fp16, per-type tables
    gemm_mma<<<dim3(D1 / 128, N_NODES / 128, NT), 256>>>(
        agg, (long long)N_NODES * F_IN, W1, (long long)F_IN * D1,
        h1r, (long long)N_NODES * D1, D1, b1, D1,
        N_NODES, D1, F_IN, 1);

    // h2 = h1r_t @ W2_t -> interleaved [node][type][128]: per-type col offset t*D2, row stride 384
    gemm_mma<<<dim3(D2 / 128, N_NODES / 128, NT), 256>>>(
        h1r, (long long)N_NODES * D1, W2, (long long)D1 * D2,
        h2, (long long)D2, NT * D2, (const float*)nullptr, 0,
        N_NODES, D2, D1, 0);

    gather2_kernel<<<N_NODES / 8, 256>>>(b2, out);
}

// round 17
// speedup vs baseline: 1.2019x; 1.0080x over previous
#include <cuda_runtime.h>
#include <cuda_fp16.h>
#include <math.h>
#include <stdint.h>

// Problem constants (fixed by setup_inputs)
#define N_NODES 32768
#define E_EDGES 524288
#define F_IN    128
#define D1      256
#define D2      128
#define NT      3
#define SEQ     16
#define NNG     512

// ---------------- scratch (device globals; no allocation allowed) ----------------
__device__ __half g_xh  [N_NODES * F_IN];            // 8 MB normalized x, fp16
__device__ __half g_agg [NT * N_NODES * F_IN];       // 24 MB aggregated xn, fp16
__device__ __half g_h1r [NT * N_NODES * D1];         // 48 MB relu(agg@W1+b1), fp16
__device__ __half g_h2  [NT * N_NODES * D2];         // 24 MB h1r@W2, fp16, [node][type][128]
__device__ float4 g_deg4[N_NODES];                   // per-node degree, types in .x/.y/.z
__device__ float4 g_dis4[N_NODES];                   // per-node rsqrt(deg+1), types in .x/.y/.z
__device__ int    g_counts[N_NODES];
__device__ int    g_rowptr[N_NODES + 1];
__device__ int    g_rank[E_EDGES];                   // per-edge rank within dst (from hist)
__device__ float4 g_meta[E_EDGES];                   // {w0,w1,w2,src-as-float} CSR by dst
__device__ float  g_colsum[F_IN];
__device__ float  g_colsq [F_IN];
__device__ float  g_mean[F_IN];
__device__ float  g_rstd[F_IN];

// ---------------- helpers ----------------
__device__ __forceinline__ uint32_t f2tf32(float f) {
    uint32_t r;
    asm("cvt.rna.tf32.f32 %0, %1;" : "=r"(r) : "f"(f));
    return r;
}
__device__ __forceinline__ void mma_tf32(float* c,
    uint32_t a0, uint32_t a1, uint32_t a2, uint32_t a3,
    uint32_t b0, uint32_t b1)
{
    asm volatile(
        "mma.sync.aligned.m16n8k8.row.col.f32.tf32.tf32.f32 "
        "{%0,%1,%2,%3}, {%4,%5,%6,%7}, {%8,%9}, {%0,%1,%2,%3};"
        : "+f"(c[0]), "+f"(c[1]), "+f"(c[2]), "+f"(c[3])
        : "r"(a0), "r"(a1), "r"(a2), "r"(a3), "r"(b0), "r"(b1));
}
__device__ __forceinline__ uint32_t pack_h2(float a, float b) {
    __half2 h = __floats2half2_rn(a, b);
    return *(uint32_t*)&h;
}
__device__ __forceinline__ float2 uph2(uint32_t u) {
    return __half22float2(*(__half2*)&u);
}

// ---------------- prep kernels (merged, role-split grids) ----------------
__global__ void zero_kernel() {
    int i = blockIdx.x * 256 + threadIdx.x;
    if (i < N_NODES) {
        g_counts[i] = 0;
        g_deg4[i] = make_float4(0.f, 0.f, 0.f, 0.f);
    }
    if (i < F_IN) { g_colsum[i] = 0.0f; g_colsq[i] = 0.0f; }
}

// prep1: blocks [0,2048) = edge histogram (rank-returning) + weighted degree (float4 quads);
//        blocks [2048,2176) = x column stats
__global__ void prep1_kernel(const float* __restrict__ x,
                             const int* __restrict__ ei, const float* __restrict__ ea) {
    int bid = blockIdx.x;
    if (bid < E_EDGES / 256) {
        int e = bid * 256 + threadIdx.x;
        int dst = ei[E_EDGES + e];
        g_rank[e] = atomicAdd(&g_counts[dst], 1);
        float* dp = (float*)&g_deg4[dst];
        atomicAdd(dp + 0, fabsf(ea[3 * e + 0]));
        atomicAdd(dp + 1, fabsf(ea[3 * e + 1]));
        atomicAdd(dp + 2, fabsf(ea[3 * e + 2]));
    } else {
        int sbid = bid - E_EDGES / 256;              // 0..127
        int c    = threadIdx.x & 127;
        int half = threadIdx.x >> 7;
        int r0   = sbid * 256 + half * 128;
        float s = 0.0f, q = 0.0f;
        for (int r = 0; r < 128; r++) {
            float v = x[(r0 + r) * F_IN + c];
            s += v; q += v * v;
        }
        atomicAdd(&g_colsum[c], s);
        atomicAdd(&g_colsq[c],  q);
    }
}

// prep2: block 0 = exclusive scan of counts; block 1 = finalize mean/rstd;
//        blocks [2, 34) = dis4 = rsqrt(deg4+1)
__global__ void prep2_kernel() {
    if (blockIdx.x == 0) {
        __shared__ int sums[1024];
        int tid  = threadIdx.x;
        int base = tid * 32;
        int vals[32];
        int s = 0;
#pragma unroll
        for (int i = 0; i < 32; i++) { int v = g_counts[base + i]; vals[i] = s; s += v; }
        sums[tid] = s;
        __syncthreads();
        for (int off = 1; off < 1024; off <<= 1) {
            int v = (tid >= off) ? sums[tid - off] : 0;
            __syncthreads();
            sums[tid] += v;
            __syncthreads();
        }
        int ex = (tid > 0) ? sums[tid - 1] : 0;
#pragma unroll
        for (int i = 0; i < 32; i++) {
            g_rowptr[base + i] = ex + vals[i];
        }
        if (tid == 1023) g_rowptr[N_NODES] = sums[1023];
    } else if (blockIdx.x == 1) {
        if (threadIdx.x < F_IN) {
            int c = threadIdx.x;
            float n = (float)N_NODES;
            float mean = g_colsum[c] / n;
            float var  = (g_colsq[c] - n * mean * mean) / (n - 1.0f);  // ddof=1
            g_mean[c] = mean;
            g_rstd[c] = rsqrtf(var);
        }
    } else {
        int i = (blockIdx.x - 2) * 1024 + threadIdx.x;
        if (i < N_NODES) {
            float4 d = g_deg4[i];
            g_dis4[i] = make_float4(rsqrtf(d.x + 1.0f), rsqrtf(d.y + 1.0f),
                                    rsqrtf(d.z + 1.0f), 0.0f);
        }
    }
}

// prep3: blocks [0,4096) = normalize x -> fp16; blocks [4096,6144) = deterministic CSR fill
__global__ void prep3_kernel(const float* __restrict__ x,
                             const int* __restrict__ ei, const float* __restrict__ ea) {
    int bid = blockIdx.x;
    if (bid < 4096) {
        int i  = bid * 256 + threadIdx.x;  // float4 index
        int c4 = (i & 31) * 4;
        float4 v = ((const float4*)x)[i];
        v.x = (v.x - g_mean[c4 + 0]) * g_rstd[c4 + 0];
        v.y = (v.y - g_mean[c4 + 1]) * g_rstd[c4 + 1];
        v.z = (v.z - g_mean[c4 + 2]) * g_rstd[c4 + 2];
        v.w = (v.w - g_mean[c4 + 3]) * g_rstd[c4 + 3];
        ((uint2*)g_xh)[i] = make_uint2(pack_h2(v.x, v.y), pack_h2(v.z, v.w));
    } else {
        int e = (bid - 4096) * 256 + threadIdx.x;
        int src = ei[e];
        int dst = ei[E_EDGES + e];
        int pos = g_rowptr[dst] + g_rank[e];     // deterministic scatter, no atomic
        float4 ds = g_dis4[src];
        float4 dd = g_dis4[dst];
        float4 m;
        m.x = ds.x * fabsf(ea[3 * e + 0]) * dd.x;
        m.y = ds.y * fabsf(ea[3 * e + 1]) * dd.y;
        m.z = ds.z * fabsf(ea[3 * e + 2]) * dd.z;
        m.w = __int_as_float(src);
        g_meta[pos] = m;
    }
}

// ---------------- fused 3-type aggregation of fp16 xn (1 warp/node, R8 config) ----------------
__global__ void gather0_kernel() {
    int lane = threadIdx.x & 31;
    int v    = blockIdx.x * 8 + (threadIdx.x >> 5);

    const uint2* __restrict__ xh = (const uint2*)g_xh;   // 32 uint2 per row (128 halves)
    int beg = g_rowptr[v];
    int end = g_rowptr[v + 1];

    float4 a0 = make_float4(0.f, 0.f, 0.f, 0.f);
    float4 a1 = make_float4(0.f, 0.f, 0.f, 0.f);
    float4 a2 = make_float4(0.f, 0.f, 0.f, 0.f);

    int j = beg;
    for (; j + 1 < end; j += 2) {
        float4 mA = __ldg(&g_meta[j]);
        float4 mB = __ldg(&g_meta[j + 1]);
        uint2 rA = xh[__float_as_int(mA.w) * 32 + lane];
        uint2 rB = xh[__float_as_int(mB.w) * 32 + lane];
        float2 fA0 = uph2(rA.x), fA1 = uph2(rA.y);
        float2 fB0 = uph2(rB.x), fB1 = uph2(rB.y);
        a0.x = fmaf(mA.x, fA0.x, a0.x); a0.y = fmaf(mA.x, fA0.y, a0.y);
        a0.z = fmaf(mA.x, fA1.x, a0.z); a0.w = fmaf(mA.x, fA1.y, a0.w);
        a1.x = fmaf(mA.y, fA0.x, a1.x); a1.y = fmaf(mA.y, fA0.y, a1.y);
        a1.z = fmaf(mA.y, fA1.x, a1.z); a1.w = fmaf(mA.y, fA1.y, a1.w);
        a2.x = fmaf(mA.z, fA0.x, a2.x); a2.y = fmaf(mA.z, fA0.y, a2.y);
        a2.z = fmaf(mA.z, fA1.x, a2.z); a2.w = fmaf(mA.z, fA1.y, a2.w);
        a0.x = fmaf(mB.x, fB0.x, a0.x); a0.y = fmaf(mB.x, fB0.y, a0.y);
        a0.z = fmaf(mB.x, fB1.x, a0.z); a0.w = fmaf(mB.x, fB1.y, a0.w);
        a1.x = fmaf(mB.y, fB0.x, a1.x); a1.y = fmaf(mB.y, fB0.y, a1.y);
        a1.z = fmaf(mB.y, fB1.x, a1.z); a1.w = fmaf(mB.y, fB1.y, a1.w);
        a2.x = fmaf(mB.z, fB0.x, a2.x); a2.y = fmaf(mB.z, fB0.y, a2.y);
        a2.z = fmaf(mB.z, fB1.x, a2.z); a2.w = fmaf(mB.z, fB1.y, a2.w);
    }
    if (j < end) {
        float4 m = __ldg(&g_meta[j]);
        uint2 r = xh[__float_as_int(m.w) * 32 + lane];
        float2 f0 = uph2(r.x), f1 = uph2(r.y);
        a0.x = fmaf(m.x, f0.x, a0.x); a0.y = fmaf(m.x, f0.y, a0.y);
        a0.z = fmaf(m.x, f1.x, a0.z); a0.w = fmaf(m.x, f1.y, a0.w);
        a1.x = fmaf(m.y, f0.x, a1.x); a1.y = fmaf(m.y, f0.y, a1.y);
        a1.z = fmaf(m.y, f1.x, a1.z); a1.w = fmaf(m.y, f1.y, a1.w);
        a2.x = fmaf(m.z, f0.x, a2.x); a2.y = fmaf(m.z, f0.y, a2.y);
        a2.z = fmaf(m.z, f1.x, a2.z); a2.w = fmaf(m.z, f1.y, a2.w);
    }

    uint2 rv = xh[v * 32 + lane];
    float2 v0 = uph2(rv.x), v1 = uph2(rv.y);
    float4 dv = g_dis4[v];
    float i0 = dv.x * dv.x;
    float i1 = dv.y * dv.y;
    float i2 = dv.z * dv.z;
    a0.x = fmaf(i0, v0.x, a0.x); a0.y = fmaf(i0, v0.y, a0.y);
    a0.z = fmaf(i0, v1.x, a0.z); a0.w = fmaf(i0, v1.y, a0.w);
    a1.x = fmaf(i1, v0.x, a1.x); a1.y = fmaf(i1, v0.y, a1.y);
    a1.z = fmaf(i1, v1.x, a1.z); a1.w = fmaf(i1, v1.y, a1.w);
    a2.x = fmaf(i2, v0.x, a2.x); a2.y = fmaf(i2, v0.y, a2.y);
    a2.z = fmaf(i2, v1.x, a2.z); a2.w = fmaf(i2, v1.y, a2.w);

    uint2* o = (uint2*)g_agg;
    o[(0 * N_NODES + v) * 32 + lane] = make_uint2(pack_h2(a0.x, a0.y), pack_h2(a0.z, a0.w));
    o[(1 * N_NODES + v) * 32 + lane] = make_uint2(pack_h2(a1.x, a1.y), pack_h2(a1.z, a1.w));
    o[(2 * N_NODES + v) * 32 + lane] = make_uint2(pack_h2(a2.x, a2.y), pack_h2(a2.z, a2.w));
}

// ---------------- tf32 mma.sync GEMM (R8 inner loop; adds C row-stride) ----------------
// C[M,N](fp16) = A(fp16)[M,K] @ W(fp32)[K,N]. Block 128x128, 8 warps, warp tile 64x32, K chunk 32.
__global__ void __launch_bounds__(256) gemm_mma(
    const __half* __restrict__ Abase, long long Astride,
    const float* __restrict__ Wbase, long long Wstride,
    __half* __restrict__ Cbase, long long Cstride, int Crowstride,
    const float* __restrict__ biasBase, int biasStride,
    int M, int N, int K, int doRelu)
{
    __shared__ uint32_t As[128][36];   // [m][k] tf32
    __shared__ uint32_t Bs[32][136];   // [k][n] tf32

    const int t = blockIdx.z;
    const __half* A = Abase + (long long)t * Astride;
    const float*  W = Wbase + (long long)t * Wstride;
    __half*       C = Cbase + (long long)t * Cstride;

    const int tid  = threadIdx.x;
    const int wid  = tid >> 5;
    const int lane = tid & 31;
    const int gid  = lane >> 2;
    const int tig  = lane & 3;
    const int wm0  = (wid & 1) * 64;
    const int wn0  = (wid >> 1) * 32;
    const int bm0  = blockIdx.y * 128;
    const int bn0  = blockIdx.x * 128;

    float acc[4][4][4];
#pragma unroll
    for (int i = 0; i < 4; i++)
#pragma unroll
        for (int j = 0; j < 4; j++)
#pragma unroll
            for (int q = 0; q < 4; q++) acc[i][j][q] = 0.0f;

    const int nch = K >> 5;
    for (int c = 0; c < nch; c++) {
        // A tile: 128 x 32 halves -> tf32
#pragma unroll
        for (int it = 0; it < 2; it++) {
            int idx = tid + it * 256;              // 0..511, 8 halves each
            int r = idx >> 2, c8 = idx & 3;
            const __half* ap = A + (long long)(bm0 + r) * K + (c << 5) + c8 * 8;
            uint4 v = *(const uint4*)ap;
            const uint32_t* pw = &v.x;
#pragma unroll
            for (int q = 0; q < 4; q++) {
                float2 f = __half22float2(*(const __half2*)&pw[q]);
                As[r][c8 * 8 + q * 2]     = f2tf32(f.x);
                As[r][c8 * 8 + q * 2 + 1] = f2tf32(f.y);
            }
        }
        // B tile: 32 x 128 floats -> tf32
#pragma unroll
        for (int it = 0; it < 4; it++) {
            int idx = tid + it * 256;
            int k = idx >> 5, n4 = idx & 31;
            float4 v = *(const float4*)(W + (long long)((c << 5) + k) * N + bn0 + n4 * 4);
            uint4 o = make_uint4(f2tf32(v.x), f2tf32(v.y), f2tf32(v.z), f2tf32(v.w));
            *(uint4*)&Bs[k][n4 * 4] = o;
        }
        __syncthreads();

#pragma unroll
        for (int ks = 0; ks < 4; ks++) {
            int kk = ks * 8;
            uint32_t bf[4][2];
#pragma unroll
            for (int nf = 0; nf < 4; nf++) {
                bf[nf][0] = Bs[kk + tig][wn0 + nf * 8 + gid];
                bf[nf][1] = Bs[kk + tig + 4][wn0 + nf * 8 + gid];
            }
#pragma unroll
            for (int mf = 0; mf < 4; mf++) {
                int r = wm0 + mf * 16 + gid;
                uint32_t a0 = As[r][kk + tig];
                uint32_t a1 = As[r + 8][kk + tig];
                uint32_t a2 = As[r][kk + tig + 4];
                uint32_t a3 = As[r + 8][kk + tig + 4];
#pragma unroll
                for (int nf = 0; nf < 4; nf++)
                    mma_tf32(acc[mf][nf], a0, a1, a2, a3, bf[nf][0], bf[nf][1]);
            }
        }
        __syncthreads();
    }

    // epilogue: bias + relu, __half2 stores (row stride Crowstride)
#pragma unroll
    for (int mf = 0; mf < 4; mf++) {
        int row = bm0 + wm0 + mf * 16 + gid;
#pragma unroll
        for (int nf = 0; nf < 4; nf++) {
            int col = bn0 + wn0 + nf * 8 + tig * 2;
            float b0 = 0.0f, b1 = 0.0f;
            if (biasBase) {
                const float* bp = biasBase + (long long)t * biasStride + col;
                b0 = bp[0]; b1 = bp[1];
            }
            float o0 = acc[mf][nf][0] + b0;
            float o1 = acc[mf][nf][1] + b1;
            float o2 = acc[mf][nf][2] + b0;
            float o3 = acc[mf][nf][3] + b1;
            if (doRelu) {
                o0 = fmaxf(o0, 0.f); o1 = fmaxf(o1, 0.f);
                o2 = fmaxf(o2, 0.f); o3 = fmaxf(o3, 0.f);
            }
            *(__half2*)(C + (long long)row * Crowstride + col)       = __floats2half2_rn(o0, o1);
            *(__half2*)(C + (long long)(row + 8) * Crowstride + col) = __floats2half2_rn(o2, o3);
        }
    }
}

// ---------------- layer-2 gather: interleaved h2 [node][type][128], 2-edge unroll ------------
__global__ void gather2_kernel(const float* __restrict__ b2, float* __restrict__ out) {
    int lane = threadIdx.x & 31;
    int v    = blockIdx.x * 8 + (threadIdx.x >> 5);

    const uint2* __restrict__ h2 = (const uint2*)g_h2;   // 96 uint2 per node (3 types x 32)
    int beg = g_rowptr[v];
    int end = g_rowptr[v + 1];

    float4 a0 = make_float4(0.f, 0.f, 0.f, 0.f);
    float4 a1 = make_float4(0.f, 0.f, 0.f, 0.f);
    float4 a2 = make_float4(0.f, 0.f, 0.f, 0.f);

    int j = beg;
    for (; j + 1 < end; j += 2) {
        float4 mA = __ldg(&g_meta[j]);
        float4 mB = __ldg(&g_meta[j + 1]);
        int sA = __float_as_int(mA.w) * 96 + lane;
        int sB = __float_as_int(mB.w) * 96 + lane;
        uint2 rA0 = h2[sA], rA1 = h2[sA + 32], rA2 = h2[sA + 64];
        uint2 rB0 = h2[sB], rB1 = h2[sB + 32], rB2 = h2[sB + 64];
        float2 fA00 = uph2(rA0.x), fA01 = uph2(rA0.y);
        float2 fA10 = uph2(rA1.x), fA11 = uph2(rA1.y);
        float2 fA20 = uph2(rA2.x), fA21 = uph2(rA2.y);
        float2 fB00 = uph2(rB0.x), fB01 = uph2(rB0.y);
        float2 fB10 = uph2(rB1.x), fB11 = uph2(rB1.y);
        float2 fB20 = uph2(rB2.x), fB21 = uph2(rB2.y);
        a0.x = fmaf(mA.x, fA00.x, a0.x); a0.y = fmaf(mA.x, fA00.y, a0.y);
        a0.z = fmaf(mA.x, fA01.x, a0.z); a0.w = fmaf(mA.x, fA01.y, a0.w);
        a1.x = fmaf(mA.y, fA10.x, a1.x); a1.y = fmaf(mA.y, fA10.y, a1.y);
        a1.z = fmaf(mA.y, fA11.x, a1.z); a1.w = fmaf(mA.y, fA11.y, a1.w);
        a2.x = fmaf(mA.z, fA20.x, a2.x); a2.y = fmaf(mA.z, fA20.y, a2.y);
        a2.z = fmaf(mA.z, fA21.x, a2.z); a2.w = fmaf(mA.z, fA21.y, a2.w);
        a0.x = fmaf(mB.x, fB00.x, a0.x); a0.y = fmaf(mB.x, fB00.y, a0.y);
        a0.z = fmaf(mB.x, fB01.x, a0.z); a0.w = fmaf(mB.x, fB01.y, a0.w);
        a1.x = fmaf(mB.y, fB10.x, a1.x); a1.y = fmaf(mB.y, fB10.y, a1.y);
        a1.z = fmaf(mB.y, fB11.x, a1.z); a1.w = fmaf(mB.y, fB11.y, a1.w);
        a2.x = fmaf(mB.z, fB20.x, a2.x); a2.y = fmaf(mB.z, fB20.y, a2.y);
        a2.z = fmaf(mB.z, fB21.x, a2.z); a2.w = fmaf(mB.z, fB21.y, a2.w);
    }
    if (j < end) {
        float4 m = __ldg(&g_meta[j]);
        int s = __float_as_int(m.w) * 96 + lane;
        uint2 r0 = h2[s], r1 = h2[s + 32], r2 = h2[s + 64];
        float2 f00 = uph2(r0.x), f01 = uph2(r0.y);
        float2 f10 = uph2(r1.x), f11 = uph2(r1.y);
        float2 f20 = uph2(r2.x), f21 = uph2(r2.y);
        a0.x = fmaf(m.x, f00.x, a0.x); a0.y = fmaf(m.x, f00.y, a0.y);
        a0.z = fmaf(m.x, f01.x, a0.z); a0.w = fmaf(m.x, f01.y, a0.w);
        a1.x = fmaf(m.y, f10.x, a1.x); a1.y = fmaf(m.y, f10.y, a1.y);
        a1.z = fmaf(m.y, f11.x, a1.z); a1.w = fmaf(m.y, f11.y, a1.w);
        a2.x = fmaf(m.z, f20.x, a2.x); a2.y = fmaf(m.z, f20.y, a2.y);
        a2.z = fmaf(m.z, f21.x, a2.z); a2.w = fmaf(m.z, f21.y, a2.w);
    }

    float4 dv = g_dis4[v];
    float i0 = dv.x * dv.x;
    float i1 = dv.y * dv.y;
    float i2 = dv.z * dv.z;
    int sv = v * 96 + lane;
    uint2 sr0 = h2[sv], sr1 = h2[sv + 32], sr2 = h2[sv + 64];
    float2 s00 = uph2(sr0.x), s01 = uph2(sr0.y);
    float2 s10 = uph2(sr1.x), s11 = uph2(sr1.y);
    float2 s20 = uph2(sr2.x), s21 = uph2(sr2.y);
    float4 bb0 = ((const float4*)(b2 + 0 * D2))[lane];
    float4 bb1 = ((const float4*)(b2 + 1 * D2))[lane];
    float4 bb2 = ((const float4*)(b2 + 2 * D2))[lane];

    a0.x = fmaxf(fmaf(i0, s00.x, a0.x) + bb0.x, 0.f);
    a0.y = fmaxf(fmaf(i0, s00.y, a0.y) + bb0.y, 0.f);
    a0.z = fmaxf(fmaf(i0, s01.x, a0.z) + bb0.z, 0.f);
    a0.w = fmaxf(fmaf(i0, s01.y, a0.w) + bb0.w, 0.f);
    a1.x = fmaxf(fmaf(i1, s10.x, a1.x) + bb1.x, 0.f);
    a1.y = fmaxf(fmaf(i1, s10.y, a1.y) + bb1.y, 0.f);
    a1.z = fmaxf(fmaf(i1, s11.x, a1.z) + bb1.z, 0.f);
    a1.w = fmaxf(fmaf(i1, s11.y, a1.w) + bb1.w, 0.f);
    a2.x = fmaxf(fmaf(i2, s20.x, a2.x) + bb2.x, 0.f);
    a2.y = fmaxf(fmaf(i2, s20.y, a2.y) + bb2.y, 0.f);
    a2.z = fmaxf(fmaf(i2, s21.x, a2.z) + bb2.z, 0.f);
    a2.w = fmaxf(fmaf(i2, s21.y, a2.w) + bb2.w, 0.f);

    int bt = v >> 13;
    int sq = (v >> 9) & 15;
    int vv = v & 511;
    int orow = bt * NNG + vv;
    long long base = ((long long)(orow * SEQ + sq)) * (NT * D2) + lane * 4;
    *(float4*)(out + base)          = a0;
    *(float4*)(out + base + D2)     = a1;
    *(float4*)(out + base + 2 * D2) = a2;
}

// ---------------- launch ----------------
extern "C" void kernel_launch(void* const* d_in, const int* in_sizes, int n_in,
                              void* d_out, int out_size) {
    const float* x  = (const float*)d_in[0];
    const float* ea = (const float*)d_in[1];
    const float* W1 = (const float*)d_in[2];
    const float* b1 = (const float*)d_in[3];
    const float* W2 = (const float*)d_in[4];
    const float* b2 = (const float*)d_in[5];
    const int*   ei = (const int*)d_in[6];
    float* out = (float*)d_out;

    __half *agg, *h1r, *h2;
    cudaGetSymbolAddress((void**)&agg, g_agg);
    cudaGetSymbolAddress((void**)&h1r, g_h1r);
    cudaGetSymbolAddress((void**)&h2,  g_h2);

    zero_kernel  <<<128, 256>>>();
    prep1_kernel <<<E_EDGES / 256 + 128, 256>>>(x, ei, ea);   // hist(rank) + stats
    prep2_kernel <<<2 + 32, 1024>>>();                         // scan + finstats + dis4
    prep3_kernel <<<4096 + E_EDGES / 256, 256>>>(x, ei, ea);   // xnorm + deterministic fill
    gather0_kernel<<<N_NODES / 8, 256>>>();

    // h1r_t = relu(agg_t @ W1_t + b1_t)   [32768,128]@[128,256] -> fp16, per-type tables
    gemm_mma<<<dim3(D1 / 128, N_NODES / 128, NT), 256>>>(
        agg, (long long)N_NODES * F_IN, W1, (long long)F_IN * D1,
        h1r, (long long)N_NODES * D1, D1, b1, D1,
        N_NODES, D1, F_IN, 1);

    // h2 = h1r_t @ W2_t -> interleaved [node][type][128]: per-type col offset t*D2, row stride 384
    gemm_mma<<<dim3(D2 / 128, N_NODES / 128, NT), 256>>>(
        h1r, (long long)N_NODES * D1, W2, (long long)D1 * D2,
        h2, (long long)D2, NT * D2, (const float*)nullptr, 0,
        N_NODES, D2, D1, 0);

    gather2_kernel<<<N_NODES / 8, 256>>>(b2, out);
}